// round 1
// baseline (speedup 1.0000x reference)
#include <cuda_runtime.h>
#include <cuda_bf16.h>
#include <math.h>

// Problem constants
#define B_   2
#define L_   2048
#define C_   1024
#define NH_  16
#define HD_  64
#define M_ROWS (B_*L_)          // 4096
#define QKV_N  (3*C_)           // 3072

// -------------------- scratch (static device globals; no allocs) ------------
__device__ float g_qkv [M_ROWS * QKV_N];      // 4096 x 3072
__device__ float g_q   [B_*NH_*L_*HD_];       // [b,h,l,d]
__device__ float g_k   [B_*NH_*L_*HD_];
__device__ float g_v   [B_*NH_*L_*HD_];
__device__ float g_attn[M_ROWS * C_];         // [b,l,h,d] == [4096,1024]

// ======================= SGEMM 128x128x16, 256 threads ======================
#define BM 128
#define BN 128
#define BK 16

__global__ __launch_bounds__(256)
void sgemm_kernel(const float* __restrict__ A, const float* __restrict__ B,
                  float* __restrict__ C, int M, int N, int K)
{
    __shared__ float As[BK][BM];
    __shared__ float Bs[BK][BN];

    const int t  = threadIdx.x;
    const int tx = t & 15;         // 0..15 -> col block of 8
    const int ty = t >> 4;         // 0..15 -> row block of 8
    const int rowBase = blockIdx.y * BM;
    const int colBase = blockIdx.x * BN;

    float acc[8][8];
    #pragma unroll
    for (int i = 0; i < 8; i++)
        #pragma unroll
        for (int j = 0; j < 8; j++) acc[i][j] = 0.f;

    for (int k0 = 0; k0 < K; k0 += BK) {
        // A tile: 128 rows x 16 cols -> As[k][m] (transposed store)
        #pragma unroll
        for (int i = 0; i < 2; i++) {
            int idx = t + i * 256;              // float4 index, 512 total
            int r   = idx >> 2;                 // 0..127
            int c4  = idx & 3;                  // 0..3
            float4 v = *(const float4*)&A[(size_t)(rowBase + r) * K + k0 + c4 * 4];
            As[c4*4+0][r] = v.x;
            As[c4*4+1][r] = v.y;
            As[c4*4+2][r] = v.z;
            As[c4*4+3][r] = v.w;
        }
        // B tile: 16 rows x 128 cols
        #pragma unroll
        for (int i = 0; i < 2; i++) {
            int idx = t + i * 256;
            int r   = idx >> 5;                 // 0..15
            int c4  = idx & 31;                 // 0..31
            *(float4*)&Bs[r][c4*4] =
                *(const float4*)&B[(size_t)(k0 + r) * N + colBase + c4 * 4];
        }
        __syncthreads();

        #pragma unroll
        for (int kk = 0; kk < BK; kk++) {
            float a[8], b[8];
            *(float4*)&a[0] = *(float4*)&As[kk][ty*8];
            *(float4*)&a[4] = *(float4*)&As[kk][ty*8+4];
            *(float4*)&b[0] = *(float4*)&Bs[kk][tx*8];
            *(float4*)&b[4] = *(float4*)&Bs[kk][tx*8+4];
            #pragma unroll
            for (int i = 0; i < 8; i++)
                #pragma unroll
                for (int j = 0; j < 8; j++)
                    acc[i][j] += a[i] * b[j];
        }
        __syncthreads();
    }

    #pragma unroll
    for (int i = 0; i < 8; i++) {
        size_t r = (size_t)(rowBase + ty*8 + i);
        *(float4*)&C[r * N + colBase + tx*8    ] = make_float4(acc[i][0],acc[i][1],acc[i][2],acc[i][3]);
        *(float4*)&C[r * N + colBase + tx*8 + 4] = make_float4(acc[i][4],acc[i][5],acc[i][6],acc[i][7]);
    }
}

// ======================= RoPE + head split =================================
// one thread per (b,l,h,pair)   pairs = HD/2 = 32
__global__ __launch_bounds__(256)
void rope_split_kernel(const float* __restrict__ qkv,
                       float* __restrict__ Q, float* __restrict__ Kd,
                       float* __restrict__ V)
{
    int idx = blockIdx.x * blockDim.x + threadIdx.x;
    const int total = M_ROWS * NH_ * (HD_/2);
    if (idx >= total) return;

    int i  = idx & 31;                 // pair index 0..31
    int h  = (idx >> 5) & 15;          // head
    int bl = idx >> 9;                 // 0..4095
    int b  = bl >> 11;                 // /2048
    int l  = bl & 2047;

    const float* row = qkv + (size_t)bl * QKV_N;
    int d0 = 2*i;

    float qe = row[h*HD_ + d0],          qo = row[h*HD_ + d0 + 1];
    float ke = row[C_   + h*HD_ + d0],   ko = row[C_   + h*HD_ + d0 + 1];
    float ve = row[2*C_ + h*HD_ + d0],   vo = row[2*C_ + h*HD_ + d0 + 1];

    // theta = l / 10000^(d0/64)
    double inv_freq = exp(-((double)d0 / 64.0) * log(10000.0));
    float theta = (float)((double)l * inv_freq);
    float s, c;
    sincosf(theta, &s, &c);

    // reference convention (sin/cos are swapped in the reference code):
    //   even = x_e*sin - x_o*cos ;  odd = x_e*cos + x_o*sin
    float qe2 = qe*s - qo*c,  qo2 = qe*c + qo*s;
    float ke2 = ke*s - ko*c,  ko2 = ke*c + ko*s;

    size_t o = (((size_t)(b*NH_ + h) * L_) + l) * HD_ + d0;
    Q[o] = qe2;  Q[o+1] = qo2;
    Kd[o] = ke2; Kd[o+1] = ko2;
    V[o] = ve;   V[o+1] = vo;
}

// ======================= Flash attention (fp32, causal) ====================
// 64x64 tiles, 256 threads; thread (ty,tx) owns 4 rows x 4 cols.
#define FA_PAD 68
#define FA_SMEM (4 * 64 * FA_PAD * 4)   // bytes

__global__ __launch_bounds__(256)
void flash_attn_kernel(const float* __restrict__ Q, const float* __restrict__ K,
                       const float* __restrict__ V, float* __restrict__ O)
{
    extern __shared__ float sm[];
    float (*QsT)[FA_PAD] = (float(*)[FA_PAD])(sm);                 // [d][r]
    float (*KsT)[FA_PAD] = (float(*)[FA_PAD])(sm + 64*FA_PAD);     // [d][j]
    float (*Vs )[FA_PAD] = (float(*)[FA_PAD])(sm + 2*64*FA_PAD);   // [j][d]
    float (*PsT)[FA_PAD] = (float(*)[FA_PAD])(sm + 3*64*FA_PAD);   // [j][r]

    const int t  = threadIdx.x;
    const int tx = t & 15;
    const int ty = t >> 4;
    const int qt = blockIdx.x;           // q tile (0..31)
    const int bh = blockIdx.y;           // 0..31
    const size_t base = (size_t)bh * L_ * HD_;

    // load Q tile (transposed)
    #pragma unroll
    for (int i = 0; i < 4; i++) {
        int idx = t + i * 256;           // 1024 float4s total
        int r   = idx >> 4;              // row within tile
        int c4  = idx & 15;
        float4 v = *(const float4*)&Q[base + (size_t)(qt*64 + r) * HD_ + c4*4];
        QsT[c4*4+0][r] = v.x; QsT[c4*4+1][r] = v.y;
        QsT[c4*4+2][r] = v.z; QsT[c4*4+3][r] = v.w;
    }

    float o[4][4];
    float m[4], lden[4];
    #pragma unroll
    for (int i = 0; i < 4; i++) {
        m[i] = -1e30f; lden[i] = 0.f;
        #pragma unroll
        for (int j = 0; j < 4; j++) o[i][j] = 0.f;
    }
    const float scale = 0.125f;          // 1/sqrt(64)

    for (int kt = 0; kt <= qt; kt++) {
        __syncthreads();                 // prev PV done (and Q load on iter 0)
        // load K (transposed) and V tiles
        #pragma unroll
        for (int i = 0; i < 4; i++) {
            int idx = t + i * 256;
            int r   = idx >> 4;
            int c4  = idx & 15;
            float4 kv = *(const float4*)&K[base + (size_t)(kt*64 + r) * HD_ + c4*4];
            KsT[c4*4+0][r] = kv.x; KsT[c4*4+1][r] = kv.y;
            KsT[c4*4+2][r] = kv.z; KsT[c4*4+3][r] = kv.w;
            *(float4*)&Vs[r][c4*4] =
                *(const float4*)&V[base + (size_t)(kt*64 + r) * HD_ + c4*4];
        }
        __syncthreads();

        // S = Q K^T  (4x4 per thread)
        float s[4][4];
        #pragma unroll
        for (int i = 0; i < 4; i++)
            #pragma unroll
            for (int j = 0; j < 4; j++) s[i][j] = 0.f;

        #pragma unroll 8
        for (int d = 0; d < 64; d++) {
            float a[4], b[4];
            *(float4*)a = *(float4*)&QsT[d][ty*4];
            *(float4*)b = *(float4*)&KsT[d][tx*4];
            #pragma unroll
            for (int i = 0; i < 4; i++)
                #pragma unroll
                for (int j = 0; j < 4; j++)
                    s[i][j] += a[i] * b[j];
        }

        // causal mask + scale
        #pragma unroll
        for (int i = 0; i < 4; i++) {
            int qrow = qt*64 + ty*4 + i;
            #pragma unroll
            for (int j = 0; j < 4; j++) {
                int kcol = kt*64 + tx*4 + j;
                s[i][j] = (kcol <= qrow) ? s[i][j] * scale : -1e30f;
            }
        }

        // online softmax (row reduce over the 16-thread tx group)
        #pragma unroll
        for (int i = 0; i < 4; i++) {
            float mx = fmaxf(fmaxf(s[i][0], s[i][1]), fmaxf(s[i][2], s[i][3]));
            mx = fmaxf(mx, __shfl_xor_sync(0xffffffffu, mx, 1));
            mx = fmaxf(mx, __shfl_xor_sync(0xffffffffu, mx, 2));
            mx = fmaxf(mx, __shfl_xor_sync(0xffffffffu, mx, 4));
            mx = fmaxf(mx, __shfl_xor_sync(0xffffffffu, mx, 8));
            float mnew  = fmaxf(m[i], mx);
            float alpha = __expf(m[i] - mnew);
            float rs = 0.f;
            #pragma unroll
            for (int j = 0; j < 4; j++) {
                float p = __expf(s[i][j] - mnew);
                s[i][j] = p;
                rs += p;
            }
            rs += __shfl_xor_sync(0xffffffffu, rs, 1);
            rs += __shfl_xor_sync(0xffffffffu, rs, 2);
            rs += __shfl_xor_sync(0xffffffffu, rs, 4);
            rs += __shfl_xor_sync(0xffffffffu, rs, 8);
            lden[i] = lden[i] * alpha + rs;
            m[i]    = mnew;
            #pragma unroll
            for (int j = 0; j < 4; j++) o[i][j] *= alpha;
            // stage P transposed for the PV gemm
            #pragma unroll
            for (int j = 0; j < 4; j++) PsT[tx*4+j][ty*4+i] = s[i][j];
        }
        __syncthreads();

        // O += P V
        #pragma unroll 8
        for (int j = 0; j < 64; j++) {
            float p4[4], v4[4];
            *(float4*)p4 = *(float4*)&PsT[j][ty*4];
            *(float4*)v4 = *(float4*)&Vs[j][tx*4];
            #pragma unroll
            for (int i = 0; i < 4; i++)
                #pragma unroll
                for (int jj = 0; jj < 4; jj++)
                    o[i][jj] += p4[i] * v4[jj];
        }
    }

    // epilogue: normalize, write in [b, l, h, d] layout (== [4096, 1024])
    int b = bh >> 4, h = bh & 15;
    #pragma unroll
    for (int i = 0; i < 4; i++) {
        float inv = 1.f / lden[i];
        int row = qt*64 + ty*4 + i;
        float4 vout = make_float4(o[i][0]*inv, o[i][1]*inv, o[i][2]*inv, o[i][3]*inv);
        size_t off = ((size_t)(b*L_ + row)) * C_ + h*HD_ + tx*4;
        *(float4*)&O[off] = vout;
    }
}

// ======================= launcher ==========================================
extern "C" void kernel_launch(void* const* d_in, const int* in_sizes, int n_in,
                              void* d_out, int out_size)
{
    const float* x     = (const float*)d_in[0];
    const float* Wqkv  = (const float*)d_in[1];
    const float* Wproj = (const float*)d_in[2];
    float* out = (float*)d_out;

    float *qkv, *q, *k, *v, *attn;
    cudaGetSymbolAddress((void**)&qkv,  g_qkv);
    cudaGetSymbolAddress((void**)&q,    g_q);
    cudaGetSymbolAddress((void**)&k,    g_k);
    cudaGetSymbolAddress((void**)&v,    g_v);
    cudaGetSymbolAddress((void**)&attn, g_attn);

    cudaFuncSetAttribute(flash_attn_kernel,
                         cudaFuncAttributeMaxDynamicSharedMemorySize, FA_SMEM);

    // 1) qkv = x @ Wqkv   [4096,1024]x[1024,3072]
    {
        dim3 grid(QKV_N / BN, M_ROWS / BM);
        sgemm_kernel<<<grid, 256>>>(x, Wqkv, qkv, M_ROWS, QKV_N, C_);
    }
    // 2) RoPE + split to [b,h,l,d]
    {
        int total = M_ROWS * NH_ * (HD_/2);
        rope_split_kernel<<<(total + 255) / 256, 256>>>(qkv, q, k, v);
    }
    // 3) causal flash attention
    {
        dim3 grid(L_ / 64, B_ * NH_);
        flash_attn_kernel<<<grid, 256, FA_SMEM>>>(q, k, v, attn);
    }
    // 4) out = attn @ Wproj   [4096,1024]x[1024,1024]
    {
        dim3 grid(C_ / BN, M_ROWS / BM);
        sgemm_kernel<<<grid, 256>>>(attn, Wproj, out, M_ROWS, C_, C_);
    }
}

// round 2
// speedup vs baseline: 2.9838x; 2.9838x over previous
#include <cuda_runtime.h>
#include <cuda_bf16.h>
#include <math.h>
#include <stdint.h>

// Problem constants
#define B_   2
#define L_   2048
#define C_   1024
#define NH_  16
#define HD_  64
#define M_ROWS (B_*L_)          // 4096
#define QKV_N  (3*C_)           // 3072

// -------------------- scratch (static device globals; no allocs) ------------
__device__ float g_qkv [M_ROWS * QKV_N];      // 4096 x 3072
__device__ float g_q   [B_*NH_*L_*HD_];       // [b,h,l,d]
__device__ float g_k   [B_*NH_*L_*HD_];
__device__ float g_v   [B_*NH_*L_*HD_];
__device__ float g_attn[M_ROWS * C_];         // [b,l,h,d] == [4096,1024]

// ======================= small PTX helpers =================================
__device__ __forceinline__ uint32_t f2tf(float x) {
    uint32_t y;
    asm("cvt.rna.tf32.f32 %0, %1;" : "=r"(y) : "f"(x));
    return y;
}
__device__ __forceinline__ void mma8(float* c,
                                     uint32_t a0, uint32_t a1, uint32_t a2, uint32_t a3,
                                     uint32_t b0, uint32_t b1) {
    asm volatile(
        "mma.sync.aligned.m16n8k8.row.col.f32.tf32.tf32.f32 "
        "{%0,%1,%2,%3}, {%4,%5,%6,%7}, {%8,%9}, {%0,%1,%2,%3};"
        : "+f"(c[0]), "+f"(c[1]), "+f"(c[2]), "+f"(c[3])
        : "r"(a0), "r"(a1), "r"(a2), "r"(a3), "r"(b0), "r"(b1));
}
__device__ __forceinline__ void cpa16(void* smem, const void* gmem) {
    uint32_t s = (uint32_t)__cvta_generic_to_shared(smem);
    asm volatile("cp.async.cg.shared.global [%0], [%1], 16;" :: "r"(s), "l"(gmem));
}
#define CP_COMMIT() asm volatile("cp.async.commit_group;")

// ======================= TF32 GEMM 128x128x32, 256 threads ==================
// C[M,N] = A[M,K] * B[K,N], all row-major fp32. tf32 via cvt.rna at fragment load.
#define GBM 128
#define GBN 128
#define GBK 32
#define ASTR 36     // A smem row stride (words): 36 mod 32 = 4 -> conflict-free frags
#define BSTR 136    // B smem row stride (words): 136 mod 32 = 8 -> conflict-free frags
#define GEMM_SMEM ((2*GBM*ASTR + 2*GBK*BSTR) * 4)

__device__ __forceinline__ void gemm_load_tile(
    const float* __restrict__ A, const float* __restrict__ B,
    float* Ad, float* Bd, int rowBase, int colBase, int k0, int K, int N, int t)
{
    #pragma unroll
    for (int i = 0; i < 4; i++) {
        int idx = t + i * 256;          // 1024 float4s for A tile
        int r   = idx >> 3;             // 0..127
        int c4  = idx & 7;              // 0..7
        cpa16(&Ad[r * ASTR + c4 * 4], &A[(size_t)(rowBase + r) * K + k0 + c4 * 4]);
    }
    #pragma unroll
    for (int i = 0; i < 4; i++) {
        int idx = t + i * 256;          // 1024 float4s for B tile
        int r   = idx >> 5;             // 0..31
        int c4  = idx & 31;             // 0..31
        cpa16(&Bd[r * BSTR + c4 * 4], &B[(size_t)(k0 + r) * N + colBase + c4 * 4]);
    }
}

__global__ __launch_bounds__(256)
void tf32_gemm(const float* __restrict__ A, const float* __restrict__ B,
               float* __restrict__ C, int M, int N, int K)
{
    extern __shared__ float sm[];
    float* As = sm;                     // [2][128][ASTR]
    float* Bs = sm + 2 * GBM * ASTR;    // [2][32][BSTR]

    const int t    = threadIdx.x;
    const int lane = t & 31;
    const int warp = t >> 5;
    const int grp  = lane >> 2;         // 0..7
    const int tig  = lane & 3;          // 0..3
    const int wm   = warp >> 2;         // 0..1  (64 rows each)
    const int wn   = warp & 3;          // 0..3  (32 cols each)
    const int rowBase = blockIdx.y * GBM;
    const int colBase = blockIdx.x * GBN;

    float acc[4][4][4];
    #pragma unroll
    for (int mi = 0; mi < 4; mi++)
        #pragma unroll
        for (int ni = 0; ni < 4; ni++)
            #pragma unroll
            for (int e = 0; e < 4; e++) acc[mi][ni][e] = 0.f;

    const int NIT = K / GBK;
    gemm_load_tile(A, B, As, Bs, rowBase, colBase, 0, K, N, t);
    CP_COMMIT();

    for (int it = 0; it < NIT; ++it) {
        if (it + 1 < NIT) {
            gemm_load_tile(A, B, As + ((it+1)&1) * GBM * ASTR,
                           Bs + ((it+1)&1) * GBK * BSTR,
                           rowBase, colBase, (it+1) * GBK, K, N, t);
            CP_COMMIT();
            asm volatile("cp.async.wait_group 1;");
        } else {
            asm volatile("cp.async.wait_group 0;");
        }
        __syncthreads();

        const float* Ac = As + (it & 1) * GBM * ASTR;
        const float* Bc = Bs + (it & 1) * GBK * BSTR;

        #pragma unroll
        for (int ks = 0; ks < 4; ks++) {
            const int k = ks * 8;
            uint32_t af[4][4];
            #pragma unroll
            for (int mi = 0; mi < 4; mi++) {
                int m0 = wm * 64 + mi * 16;
                af[mi][0] = f2tf(Ac[(m0 + grp    ) * ASTR + k + tig    ]);
                af[mi][1] = f2tf(Ac[(m0 + grp + 8) * ASTR + k + tig    ]);
                af[mi][2] = f2tf(Ac[(m0 + grp    ) * ASTR + k + tig + 4]);
                af[mi][3] = f2tf(Ac[(m0 + grp + 8) * ASTR + k + tig + 4]);
            }
            uint32_t bf[4][2];
            #pragma unroll
            for (int ni = 0; ni < 4; ni++) {
                int n0 = wn * 32 + ni * 8;
                bf[ni][0] = f2tf(Bc[(k + tig    ) * BSTR + n0 + grp]);
                bf[ni][1] = f2tf(Bc[(k + tig + 4) * BSTR + n0 + grp]);
            }
            #pragma unroll
            for (int mi = 0; mi < 4; mi++)
                #pragma unroll
                for (int ni = 0; ni < 4; ni++)
                    mma8(acc[mi][ni], af[mi][0], af[mi][1], af[mi][2], af[mi][3],
                         bf[ni][0], bf[ni][1]);
        }
        __syncthreads();
    }

    // epilogue: c0,c1 at (row, 2tig / 2tig+1); c2,c3 at row+8
    #pragma unroll
    for (int mi = 0; mi < 4; mi++) {
        #pragma unroll
        for (int ni = 0; ni < 4; ni++) {
            int row = rowBase + wm * 64 + mi * 16 + grp;
            int col = colBase + wn * 32 + ni * 8 + 2 * tig;
            float2 v0 = make_float2(acc[mi][ni][0], acc[mi][ni][1]);
            float2 v1 = make_float2(acc[mi][ni][2], acc[mi][ni][3]);
            *(float2*)&C[(size_t)row       * N + col] = v0;
            *(float2*)&C[(size_t)(row + 8) * N + col] = v1;
        }
    }
}

// ======================= RoPE + head split =================================
__global__ __launch_bounds__(256)
void rope_split_kernel(const float* __restrict__ qkv,
                       float* __restrict__ Q, float* __restrict__ Kd,
                       float* __restrict__ V)
{
    int idx = blockIdx.x * blockDim.x + threadIdx.x;
    const int total = M_ROWS * NH_ * (HD_/2);
    if (idx >= total) return;

    int i  = idx & 31;
    int h  = (idx >> 5) & 15;
    int bl = idx >> 9;
    int b  = bl >> 11;
    int l  = bl & 2047;

    const float* row = qkv + (size_t)bl * QKV_N;
    int d0 = 2*i;

    float qe = row[h*HD_ + d0],          qo = row[h*HD_ + d0 + 1];
    float ke = row[C_   + h*HD_ + d0],   ko = row[C_   + h*HD_ + d0 + 1];
    float ve = row[2*C_ + h*HD_ + d0],   vo = row[2*C_ + h*HD_ + d0 + 1];

    double inv_freq = exp(-((double)d0 / 64.0) * log(10000.0));
    float theta = (float)((double)l * inv_freq);
    float s, c;
    sincosf(theta, &s, &c);

    // reference convention (sin/cos swapped):
    float qe2 = qe*s - qo*c,  qo2 = qe*c + qo*s;
    float ke2 = ke*s - ko*c,  ko2 = ke*c + ko*s;

    size_t o = (((size_t)(b*NH_ + h) * L_) + l) * HD_ + d0;
    Q[o] = qe2;  Q[o+1] = qo2;
    Kd[o] = ke2; Kd[o+1] = ko2;
    V[o] = ve;   V[o+1] = vo;
}

// ======================= Flash attention (tf32 mma, causal) ================
// Q tile 64 rows, 128 threads = 4 warps; each warp owns 16 q-rows.
#define QSTR 68
#define KSTR 68
#define VSTR 72
#define PSTR 68
#define OFF_K (64*QSTR)
#define OFF_V (OFF_K + 64*KSTR)
#define OFF_P (OFF_V + 64*VSTR)
#define FA_SMEM ((OFF_P + 64*PSTR) * 4)

__global__ __launch_bounds__(128)
void flash_tf32(const float* __restrict__ Q, const float* __restrict__ K,
                const float* __restrict__ V, float* __restrict__ O)
{
    extern __shared__ float sm[];
    float* Qs = sm;
    float* Ks = sm + OFF_K;
    float* Vs = sm + OFF_V;
    float* Ps = sm + OFF_P;

    const int t    = threadIdx.x;
    const int lane = t & 31;
    const int warp = t >> 5;
    const int grp  = lane >> 2;
    const int tig  = lane & 3;
    const int qt   = blockIdx.x;         // q tile 0..31
    const int bh   = blockIdx.y;         // 0..31
    const size_t base = (size_t)bh * L_ * HD_;
    const int m0 = warp * 16;

    // load Q tile (tf32-rounded into smem)
    #pragma unroll
    for (int i = 0; i < 8; i++) {
        int idx = t + i * 128;           // 1024 float4s
        int r   = idx >> 4;
        int c4  = idx & 15;
        float4 v = *(const float4*)&Q[base + (size_t)(qt*64 + r) * HD_ + c4*4];
        uint4 u = make_uint4(f2tf(v.x), f2tf(v.y), f2tf(v.z), f2tf(v.w));
        *(uint4*)&Qs[r * QSTR + c4 * 4] = u;
    }

    float o[8][4];
    #pragma unroll
    for (int ni = 0; ni < 8; ni++)
        #pragma unroll
        for (int e = 0; e < 4; e++) o[ni][e] = 0.f;
    float mA = -1e30f, mB = -1e30f, lA = 0.f, lB = 0.f;
    const float scale = 0.125f;

    for (int kt = 0; kt <= qt; kt++) {
        __syncthreads();                 // prev PV done; safe to overwrite K/V/P
        #pragma unroll
        for (int i = 0; i < 8; i++) {
            int idx = t + i * 128;
            int r   = idx >> 4;
            int c4  = idx & 15;
            float4 kv = *(const float4*)&K[base + (size_t)(kt*64 + r) * HD_ + c4*4];
            *(uint4*)&Ks[r * KSTR + c4 * 4] =
                make_uint4(f2tf(kv.x), f2tf(kv.y), f2tf(kv.z), f2tf(kv.w));
            float4 vv = *(const float4*)&V[base + (size_t)(kt*64 + r) * HD_ + c4*4];
            *(uint4*)&Vs[r * VSTR + c4 * 4] =
                make_uint4(f2tf(vv.x), f2tf(vv.y), f2tf(vv.z), f2tf(vv.w));
        }
        __syncthreads();

        // S = Q K^T : warp computes 16 x 64
        float s[8][4];
        #pragma unroll
        for (int ni = 0; ni < 8; ni++)
            #pragma unroll
            for (int e = 0; e < 4; e++) s[ni][e] = 0.f;

        #pragma unroll
        for (int ks = 0; ks < 8; ks++) {
            const int k = ks * 8;
            uint32_t a0 = __float_as_uint(Qs[(m0 + grp    ) * QSTR + k + tig    ]);
            uint32_t a1 = __float_as_uint(Qs[(m0 + grp + 8) * QSTR + k + tig    ]);
            uint32_t a2 = __float_as_uint(Qs[(m0 + grp    ) * QSTR + k + tig + 4]);
            uint32_t a3 = __float_as_uint(Qs[(m0 + grp + 8) * QSTR + k + tig + 4]);
            #pragma unroll
            for (int ni = 0; ni < 8; ni++) {
                uint32_t b0 = __float_as_uint(Ks[(ni*8 + grp) * KSTR + k + tig    ]);
                uint32_t b1 = __float_as_uint(Ks[(ni*8 + grp) * KSTR + k + tig + 4]);
                mma8(s[ni], a0, a1, a2, a3, b0, b1);
            }
        }

        // scale (+ causal mask only on the diagonal tile)
        if (kt == qt) {
            #pragma unroll
            for (int ni = 0; ni < 8; ni++)
                #pragma unroll
                for (int e = 0; e < 4; e++) {
                    int col = kt*64 + ni*8 + 2*tig + (e & 1);
                    int row = qt*64 + m0 + grp + ((e & 2) ? 8 : 0);
                    s[ni][e] = (col <= row) ? s[ni][e] * scale : -1e30f;
                }
        } else {
            #pragma unroll
            for (int ni = 0; ni < 8; ni++)
                #pragma unroll
                for (int e = 0; e < 4; e++) s[ni][e] *= scale;
        }

        // online softmax: row A = (grp), row B = (grp+8); reduce over tig group
        float mxA = -1e30f, mxB = -1e30f;
        #pragma unroll
        for (int ni = 0; ni < 8; ni++) {
            mxA = fmaxf(mxA, fmaxf(s[ni][0], s[ni][1]));
            mxB = fmaxf(mxB, fmaxf(s[ni][2], s[ni][3]));
        }
        mxA = fmaxf(mxA, __shfl_xor_sync(0xffffffffu, mxA, 1));
        mxA = fmaxf(mxA, __shfl_xor_sync(0xffffffffu, mxA, 2));
        mxB = fmaxf(mxB, __shfl_xor_sync(0xffffffffu, mxB, 1));
        mxB = fmaxf(mxB, __shfl_xor_sync(0xffffffffu, mxB, 2));

        float mnA = fmaxf(mA, mxA), mnB = fmaxf(mB, mxB);
        float aA = __expf(mA - mnA), aB = __expf(mB - mnB);
        float sA = 0.f, sB = 0.f;
        #pragma unroll
        for (int ni = 0; ni < 8; ni++) {
            s[ni][0] = __expf(s[ni][0] - mnA);
            s[ni][1] = __expf(s[ni][1] - mnA);
            s[ni][2] = __expf(s[ni][2] - mnB);
            s[ni][3] = __expf(s[ni][3] - mnB);
            sA += s[ni][0] + s[ni][1];
            sB += s[ni][2] + s[ni][3];
        }
        sA += __shfl_xor_sync(0xffffffffu, sA, 1);
        sA += __shfl_xor_sync(0xffffffffu, sA, 2);
        sB += __shfl_xor_sync(0xffffffffu, sB, 1);
        sB += __shfl_xor_sync(0xffffffffu, sB, 2);
        lA = lA * aA + sA;  lB = lB * aB + sB;
        mA = mnA;           mB = mnB;
        #pragma unroll
        for (int ni = 0; ni < 8; ni++) {
            o[ni][0] *= aA; o[ni][1] *= aA;
            o[ni][2] *= aB; o[ni][3] *= aB;
        }

        // stage P (tf32-rounded) in smem for the PV mma
        #pragma unroll
        for (int ni = 0; ni < 8; ni++) {
            int c = ni*8 + 2*tig;
            *(uint2*)&Ps[(m0 + grp    ) * PSTR + c] =
                make_uint2(f2tf(s[ni][0]), f2tf(s[ni][1]));
            *(uint2*)&Ps[(m0 + grp + 8) * PSTR + c] =
                make_uint2(f2tf(s[ni][2]), f2tf(s[ni][3]));
        }
        __syncthreads();

        // O += P V : M=16(warp), N=64(d), K=64(j)
        #pragma unroll
        for (int ks = 0; ks < 8; ks++) {
            const int j = ks * 8;
            uint32_t a0 = __float_as_uint(Ps[(m0 + grp    ) * PSTR + j + tig    ]);
            uint32_t a1 = __float_as_uint(Ps[(m0 + grp + 8) * PSTR + j + tig    ]);
            uint32_t a2 = __float_as_uint(Ps[(m0 + grp    ) * PSTR + j + tig + 4]);
            uint32_t a3 = __float_as_uint(Ps[(m0 + grp + 8) * PSTR + j + tig + 4]);
            #pragma unroll
            for (int ni = 0; ni < 8; ni++) {
                uint32_t b0 = __float_as_uint(Vs[(j + tig    ) * VSTR + ni*8 + grp]);
                uint32_t b1 = __float_as_uint(Vs[(j + tig + 4) * VSTR + ni*8 + grp]);
                mma8(o[ni], a0, a1, a2, a3, b0, b1);
            }
        }
    }

    // epilogue: normalize, write [b, l, h, d]
    int b = bh >> 4, h = bh & 15;
    float iA = 1.f / lA, iB = 1.f / lB;
    #pragma unroll
    for (int ni = 0; ni < 8; ni++) {
        int c  = ni*8 + 2*tig;
        int rA = qt*64 + m0 + grp;
        size_t offA = ((size_t)(b*L_ + rA    )) * C_ + h*HD_ + c;
        size_t offB = ((size_t)(b*L_ + rA + 8)) * C_ + h*HD_ + c;
        *(float2*)&O[offA] = make_float2(o[ni][0]*iA, o[ni][1]*iA);
        *(float2*)&O[offB] = make_float2(o[ni][2]*iB, o[ni][3]*iB);
    }
}

// ======================= launcher ==========================================
extern "C" void kernel_launch(void* const* d_in, const int* in_sizes, int n_in,
                              void* d_out, int out_size)
{
    const float* x     = (const float*)d_in[0];
    const float* Wqkv  = (const float*)d_in[1];
    const float* Wproj = (const float*)d_in[2];
    float* out = (float*)d_out;

    float *qkv, *q, *k, *v, *attn;
    cudaGetSymbolAddress((void**)&qkv,  g_qkv);
    cudaGetSymbolAddress((void**)&q,    g_q);
    cudaGetSymbolAddress((void**)&k,    g_k);
    cudaGetSymbolAddress((void**)&v,    g_v);
    cudaGetSymbolAddress((void**)&attn, g_attn);

    cudaFuncSetAttribute(tf32_gemm,
                         cudaFuncAttributeMaxDynamicSharedMemorySize, GEMM_SMEM);
    cudaFuncSetAttribute(flash_tf32,
                         cudaFuncAttributeMaxDynamicSharedMemorySize, FA_SMEM);

    // 1) qkv = x @ Wqkv
    {
        dim3 grid(QKV_N / GBN, M_ROWS / GBM);
        tf32_gemm<<<grid, 256, GEMM_SMEM>>>(x, Wqkv, qkv, M_ROWS, QKV_N, C_);
    }
    // 2) RoPE + split to [b,h,l,d]
    {
        int total = M_ROWS * NH_ * (HD_/2);
        rope_split_kernel<<<(total + 255) / 256, 256>>>(qkv, q, k, v);
    }
    // 3) causal flash attention (tf32 tensor cores)
    {
        dim3 grid(L_ / 64, B_ * NH_);
        flash_tf32<<<grid, 128, FA_SMEM>>>(q, k, v, attn);
    }
    // 4) out = attn @ Wproj
    {
        dim3 grid(C_ / GBN, M_ROWS / GBM);
        tf32_gemm<<<grid, 256, GEMM_SMEM>>>(attn, Wproj, out, M_ROWS, C_, C_);
    }
}

// round 3
// speedup vs baseline: 3.0309x; 1.0158x over previous
#include <cuda_runtime.h>
#include <cuda_bf16.h>
#include <math.h>
#include <stdint.h>

// Problem constants
#define B_   2
#define L_   2048
#define C_   1024
#define NH_  16
#define HD_  64
#define M_ROWS (B_*L_)          // 4096
#define QKV_N  (3*C_)           // 3072

// -------------------- scratch (static device globals) -----------------------
__device__ float g_qkv [M_ROWS * QKV_N];
__device__ float g_q   [B_*NH_*L_*HD_];       // [b,h,l,d]
__device__ float g_k   [B_*NH_*L_*HD_];
__device__ float g_v   [B_*NH_*L_*HD_];
__device__ float g_attn[M_ROWS * C_];         // [b,l,h,d]

// ======================= small PTX helpers =================================
__device__ __forceinline__ uint32_t f2tf(float x) {
    uint32_t y;
    asm("cvt.rna.tf32.f32 %0, %1;" : "=r"(y) : "f"(x));
    return y;
}
__device__ __forceinline__ float ex2(float x) {
    float y;
    asm("ex2.approx.f32 %0, %1;" : "=f"(y) : "f"(x));
    return y;
}
__device__ __forceinline__ void mma8(float* c,
                                     uint32_t a0, uint32_t a1, uint32_t a2, uint32_t a3,
                                     uint32_t b0, uint32_t b1) {
    asm volatile(
        "mma.sync.aligned.m16n8k8.row.col.f32.tf32.tf32.f32 "
        "{%0,%1,%2,%3}, {%4,%5,%6,%7}, {%8,%9}, {%0,%1,%2,%3};"
        : "+f"(c[0]), "+f"(c[1]), "+f"(c[2]), "+f"(c[3])
        : "r"(a0), "r"(a1), "r"(a2), "r"(a3), "r"(b0), "r"(b1));
}
__device__ __forceinline__ void cpa16(void* smem, const void* gmem) {
    uint32_t s = (uint32_t)__cvta_generic_to_shared(smem);
    asm volatile("cp.async.cg.shared.global [%0], [%1], 16;" :: "r"(s), "l"(gmem));
}
#define CP_COMMIT() asm volatile("cp.async.commit_group;")
#define CP_WAIT0()  asm volatile("cp.async.wait_group 0;")

// ======================= TF32 GEMM 128x128x32, 256 threads ==================
#define GBM 128
#define GBN 128
#define GBK 32
#define ASTR 36
#define BSTR 136
#define GEMM_SMEM ((2*GBM*ASTR + 2*GBK*BSTR) * 4)

__device__ __forceinline__ void gemm_load_tile(
    const float* __restrict__ A, const float* __restrict__ B,
    float* Ad, float* Bd, int rowBase, int colBase, int k0, int K, int N, int t)
{
    #pragma unroll
    for (int i = 0; i < 4; i++) {
        int idx = t + i * 256;
        int r   = idx >> 3;
        int c4  = idx & 7;
        cpa16(&Ad[r * ASTR + c4 * 4], &A[(size_t)(rowBase + r) * K + k0 + c4 * 4]);
    }
    #pragma unroll
    for (int i = 0; i < 4; i++) {
        int idx = t + i * 256;
        int r   = idx >> 5;
        int c4  = idx & 31;
        cpa16(&Bd[r * BSTR + c4 * 4], &B[(size_t)(k0 + r) * N + colBase + c4 * 4]);
    }
}

__global__ __launch_bounds__(256, 2)
void tf32_gemm(const float* __restrict__ A, const float* __restrict__ B,
               float* __restrict__ C, int M, int N, int K)
{
    extern __shared__ float sm[];
    float* As = sm;
    float* Bs = sm + 2 * GBM * ASTR;

    const int t    = threadIdx.x;
    const int lane = t & 31;
    const int warp = t >> 5;
    const int grp  = lane >> 2;
    const int tig  = lane & 3;
    const int wm   = warp >> 2;
    const int wn   = warp & 3;
    const int rowBase = blockIdx.y * GBM;
    const int colBase = blockIdx.x * GBN;

    float acc[4][4][4];
    #pragma unroll
    for (int mi = 0; mi < 4; mi++)
        #pragma unroll
        for (int ni = 0; ni < 4; ni++)
            #pragma unroll
            for (int e = 0; e < 4; e++) acc[mi][ni][e] = 0.f;

    const int NIT = K / GBK;
    gemm_load_tile(A, B, As, Bs, rowBase, colBase, 0, K, N, t);
    CP_COMMIT();

    for (int it = 0; it < NIT; ++it) {
        CP_WAIT0();             // stage `it` is the only outstanding group
        __syncthreads();        // visible to all; all threads done with other buf

        if (it + 1 < NIT) {     // prefetch overlaps the whole compute below
            gemm_load_tile(A, B, As + ((it+1)&1) * GBM * ASTR,
                           Bs + ((it+1)&1) * GBK * BSTR,
                           rowBase, colBase, (it+1) * GBK, K, N, t);
            CP_COMMIT();
        }

        const float* Ac = As + (it & 1) * GBM * ASTR;
        const float* Bc = Bs + (it & 1) * GBK * BSTR;

        #pragma unroll
        for (int ks = 0; ks < 4; ks++) {
            const int k = ks * 8;
            uint32_t af[4][4];
            #pragma unroll
            for (int mi = 0; mi < 4; mi++) {
                int m0 = wm * 64 + mi * 16;
                af[mi][0] = f2tf(Ac[(m0 + grp    ) * ASTR + k + tig    ]);
                af[mi][1] = f2tf(Ac[(m0 + grp + 8) * ASTR + k + tig    ]);
                af[mi][2] = f2tf(Ac[(m0 + grp    ) * ASTR + k + tig + 4]);
                af[mi][3] = f2tf(Ac[(m0 + grp + 8) * ASTR + k + tig + 4]);
            }
            uint32_t bf[4][2];
            #pragma unroll
            for (int ni = 0; ni < 4; ni++) {
                int n0 = wn * 32 + ni * 8;
                bf[ni][0] = f2tf(Bc[(k + tig    ) * BSTR + n0 + grp]);
                bf[ni][1] = f2tf(Bc[(k + tig + 4) * BSTR + n0 + grp]);
            }
            #pragma unroll
            for (int mi = 0; mi < 4; mi++)
                #pragma unroll
                for (int ni = 0; ni < 4; ni++)
                    mma8(acc[mi][ni], af[mi][0], af[mi][1], af[mi][2], af[mi][3],
                         bf[ni][0], bf[ni][1]);
        }
        // no trailing sync: next iteration's writes target the other buffer,
        // and the top-of-loop sync orders reads vs. the it+2 overwrite.
    }

    #pragma unroll
    for (int mi = 0; mi < 4; mi++) {
        #pragma unroll
        for (int ni = 0; ni < 4; ni++) {
            int row = rowBase + wm * 64 + mi * 16 + grp;
            int col = colBase + wn * 32 + ni * 8 + 2 * tig;
            *(float2*)&C[(size_t)row       * N + col] = make_float2(acc[mi][ni][0], acc[mi][ni][1]);
            *(float2*)&C[(size_t)(row + 8) * N + col] = make_float2(acc[mi][ni][2], acc[mi][ni][3]);
        }
    }
}

// ======================= RoPE + head split =================================
__global__ __launch_bounds__(256)
void rope_split_kernel(const float* __restrict__ qkv,
                       float* __restrict__ Q, float* __restrict__ Kd,
                       float* __restrict__ V)
{
    int idx = blockIdx.x * blockDim.x + threadIdx.x;
    const int total = M_ROWS * NH_ * (HD_/2);
    if (idx >= total) return;

    int i  = idx & 31;
    int h  = (idx >> 5) & 15;
    int bl = idx >> 9;
    int b  = bl >> 11;
    int l  = bl & 2047;

    const float* row = qkv + (size_t)bl * QKV_N;
    int d0 = 2*i;

    float qe = row[h*HD_ + d0],          qo = row[h*HD_ + d0 + 1];
    float ke = row[C_   + h*HD_ + d0],   ko = row[C_   + h*HD_ + d0 + 1];
    float ve = row[2*C_ + h*HD_ + d0],   vo = row[2*C_ + h*HD_ + d0 + 1];

    double inv_freq = exp(-((double)d0 / 64.0) * log(10000.0));
    float theta = (float)((double)l * inv_freq);
    float s, c;
    sincosf(theta, &s, &c);

    // reference convention (sin/cos swapped):
    float qe2 = qe*s - qo*c,  qo2 = qe*c + qo*s;
    float ke2 = ke*s - ko*c,  ko2 = ke*c + ko*s;

    size_t o = (((size_t)(b*NH_ + h) * L_) + l) * HD_ + d0;
    Q[o] = qe2;  Q[o+1] = qo2;
    Kd[o] = ke2; Kd[o+1] = ko2;
    V[o] = ve;   V[o+1] = vo;
}

// ======================= Flash attention v2 (tf32 mma, causal) =============
// Q tile 128 rows, 256 threads = 8 warps, warp owns 16 rows.
// K/V cp.async double-buffered; in-place tf32 convert pass; Q frags in regs.
#define FKSTR 68
#define FVSTR 72
#define FPSTR 68
#define KS_STAGE (64*FKSTR)
#define VS_STAGE (64*FVSTR)
#define OFF_FV (2*KS_STAGE)
#define OFF_FP (2*KS_STAGE + 2*VS_STAGE)
#define FA_SMEM ((2*KS_STAGE + 2*VS_STAGE + 128*FPSTR) * 4)

__global__ __launch_bounds__(256)
void flash_tf32(const float* __restrict__ Q, const float* __restrict__ K,
                const float* __restrict__ V, float* __restrict__ O)
{
    extern __shared__ float sm[];
    float* Ks = sm;
    float* Vs = sm + OFF_FV;
    float* Ps = sm + OFF_FP;

    const int t    = threadIdx.x;
    const int lane = t & 31;
    const int warp = t >> 5;
    const int grp  = lane >> 2;
    const int tig  = lane & 3;
    const int qt   = (gridDim.x - 1) - blockIdx.x;   // heavy blocks first
    const int bh   = blockIdx.y;
    const size_t base = (size_t)bh * L_ * HD_;
    const int R0 = qt * 128 + warp * 16;             // warp's first q-row

    // ---- Q fragments in registers, scale folded: 1/8 * log2(e) ----
    const float qsc = 0.125f * 1.4426950408889634f;
    uint32_t aq[8][4];
    {
        const float* Qp = Q + base + (size_t)R0 * HD_;
        #pragma unroll
        for (int ks = 0; ks < 8; ks++) {
            int c = 8 * ks + tig;
            aq[ks][0] = f2tf(Qp[(grp    ) * HD_ + c    ] * qsc);
            aq[ks][1] = f2tf(Qp[(grp + 8) * HD_ + c    ] * qsc);
            aq[ks][2] = f2tf(Qp[(grp    ) * HD_ + c + 4] * qsc);
            aq[ks][3] = f2tf(Qp[(grp + 8) * HD_ + c + 4] * qsc);
        }
    }

    float o[8][4];
    #pragma unroll
    for (int ni = 0; ni < 8; ni++)
        #pragma unroll
        for (int e = 0; e < 4; e++) o[ni][e] = 0.f;
    float mA = -1e30f, mB = -1e30f, lA = 0.f, lB = 0.f;

    const int nkt = 2 * qt + 2;

    // prologue: stage 0
    {
        const float* Kg = K + base;
        const float* Vg = V + base;
        #pragma unroll
        for (int i = 0; i < 4; i++) {
            int idx = t + i * 256;
            int r   = idx >> 4;
            int c4  = idx & 15;
            cpa16(&Ks[r * FKSTR + c4 * 4], &Kg[(size_t)r * HD_ + c4 * 4]);
            cpa16(&Vs[r * FVSTR + c4 * 4], &Vg[(size_t)r * HD_ + c4 * 4]);
        }
        CP_COMMIT();
    }

    for (int kt = 0; kt < nkt; kt++) {
        const int p = kt & 1;
        CP_WAIT0();
        __syncthreads();

        if (kt + 1 < nkt) {                 // prefetch next K/V tile
            const float* Kg = K + base + (size_t)(kt + 1) * 64 * HD_;
            const float* Vg = V + base + (size_t)(kt + 1) * 64 * HD_;
            float* Kn = Ks + (p ^ 1) * KS_STAGE;
            float* Vn = Vs + (p ^ 1) * VS_STAGE;
            #pragma unroll
            for (int i = 0; i < 4; i++) {
                int idx = t + i * 256;
                int r   = idx >> 4;
                int c4  = idx & 15;
                cpa16(&Kn[r * FKSTR + c4 * 4], &Kg[(size_t)r * HD_ + c4 * 4]);
                cpa16(&Vn[r * FVSTR + c4 * 4], &Vg[(size_t)r * HD_ + c4 * 4]);
            }
            CP_COMMIT();
        }

        // ---- in-place fp32 -> tf32 convert of stage p ----
        float* Kc = Ks + p * KS_STAGE;
        float* Vc = Vs + p * VS_STAGE;
        #pragma unroll
        for (int i = 0; i < 4; i++) {
            int idx = t + i * 256;
            int r   = idx >> 4;
            int c4  = idx & 15;
            float4 kv = *(float4*)&Kc[r * FKSTR + c4 * 4];
            *(uint4*)&Kc[r * FKSTR + c4 * 4] =
                make_uint4(f2tf(kv.x), f2tf(kv.y), f2tf(kv.z), f2tf(kv.w));
            float4 vv = *(float4*)&Vc[r * FVSTR + c4 * 4];
            *(uint4*)&Vc[r * FVSTR + c4 * 4] =
                make_uint4(f2tf(vv.x), f2tf(vv.y), f2tf(vv.z), f2tf(vv.w));
        }
        __syncthreads();

        const bool active = (kt * 64 <= R0 + 15);
        if (active) {
            // ---- S = Q K^T (16 x 64 per warp) ----
            float s[8][4];
            #pragma unroll
            for (int ni = 0; ni < 8; ni++)
                #pragma unroll
                for (int e = 0; e < 4; e++) s[ni][e] = 0.f;

            #pragma unroll
            for (int ks = 0; ks < 8; ks++) {
                const int k = ks * 8;
                #pragma unroll
                for (int ni = 0; ni < 8; ni++) {
                    uint32_t b0 = __float_as_uint(Kc[(ni*8 + grp) * FKSTR + k + tig    ]);
                    uint32_t b1 = __float_as_uint(Kc[(ni*8 + grp) * FKSTR + k + tig + 4]);
                    mma8(s[ni], aq[ks][0], aq[ks][1], aq[ks][2], aq[ks][3], b0, b1);
                }
            }

            // causal mask (only near the diagonal)
            if (kt * 64 + 63 > R0) {
                #pragma unroll
                for (int ni = 0; ni < 8; ni++)
                    #pragma unroll
                    for (int e = 0; e < 4; e++) {
                        int col = kt*64 + ni*8 + 2*tig + (e & 1);
                        int row = R0 + grp + ((e & 2) ? 8 : 0);
                        if (col > row) s[ni][e] = -1e30f;
                    }
            }

            // ---- online softmax (exp2 domain) ----
            float mxA = -1e30f, mxB = -1e30f;
            #pragma unroll
            for (int ni = 0; ni < 8; ni++) {
                mxA = fmaxf(mxA, fmaxf(s[ni][0], s[ni][1]));
                mxB = fmaxf(mxB, fmaxf(s[ni][2], s[ni][3]));
            }
            mxA = fmaxf(mxA, __shfl_xor_sync(0xffffffffu, mxA, 1));
            mxA = fmaxf(mxA, __shfl_xor_sync(0xffffffffu, mxA, 2));
            mxB = fmaxf(mxB, __shfl_xor_sync(0xffffffffu, mxB, 1));
            mxB = fmaxf(mxB, __shfl_xor_sync(0xffffffffu, mxB, 2));

            float mnA = fmaxf(mA, mxA), mnB = fmaxf(mB, mxB);
            float aA = ex2(mA - mnA), aB = ex2(mB - mnB);
            float sA = 0.f, sB = 0.f;
            #pragma unroll
            for (int ni = 0; ni < 8; ni++) {
                s[ni][0] = ex2(s[ni][0] - mnA);
                s[ni][1] = ex2(s[ni][1] - mnA);
                s[ni][2] = ex2(s[ni][2] - mnB);
                s[ni][3] = ex2(s[ni][3] - mnB);
                sA += s[ni][0] + s[ni][1];
                sB += s[ni][2] + s[ni][3];
            }
            sA += __shfl_xor_sync(0xffffffffu, sA, 1);
            sA += __shfl_xor_sync(0xffffffffu, sA, 2);
            sB += __shfl_xor_sync(0xffffffffu, sB, 1);
            sB += __shfl_xor_sync(0xffffffffu, sB, 2);
            lA = lA * aA + sA;  lB = lB * aB + sB;
            mA = mnA;           mB = mnB;
            #pragma unroll
            for (int ni = 0; ni < 8; ni++) {
                o[ni][0] *= aA; o[ni][1] *= aA;
                o[ni][2] *= aB; o[ni][3] *= aB;
            }

            // ---- stage P (per-warp region; warp-local sync only) ----
            float* Pw = Ps + warp * 16 * FPSTR;
            #pragma unroll
            for (int ni = 0; ni < 8; ni++) {
                int c = ni*8 + 2*tig;
                *(uint2*)&Pw[(grp    ) * FPSTR + c] = make_uint2(f2tf(s[ni][0]), f2tf(s[ni][1]));
                *(uint2*)&Pw[(grp + 8) * FPSTR + c] = make_uint2(f2tf(s[ni][2]), f2tf(s[ni][3]));
            }
            __syncwarp();

            // ---- O += P V ----
            #pragma unroll
            for (int ks = 0; ks < 8; ks++) {
                const int j = ks * 8;
                uint32_t a0 = __float_as_uint(Pw[(grp    ) * FPSTR + j + tig    ]);
                uint32_t a1 = __float_as_uint(Pw[(grp + 8) * FPSTR + j + tig    ]);
                uint32_t a2 = __float_as_uint(Pw[(grp    ) * FPSTR + j + tig + 4]);
                uint32_t a3 = __float_as_uint(Pw[(grp + 8) * FPSTR + j + tig + 4]);
                #pragma unroll
                for (int ni = 0; ni < 8; ni++) {
                    uint32_t b0 = __float_as_uint(Vc[(j + tig    ) * FVSTR + ni*8 + grp]);
                    uint32_t b1 = __float_as_uint(Vc[(j + tig + 4) * FVSTR + ni*8 + grp]);
                    mma8(o[ni], a0, a1, a2, a3, b0, b1);
                }
            }
        }
    }

    // ---- epilogue: normalize, write [b, l, h, d] ----
    int b = bh >> 4, h = bh & 15;
    float iA = 1.f / lA, iB = 1.f / lB;
    #pragma unroll
    for (int ni = 0; ni < 8; ni++) {
        int c = ni*8 + 2*tig;
        size_t offA = ((size_t)(b*L_ + R0 + grp    )) * C_ + h*HD_ + c;
        size_t offB = ((size_t)(b*L_ + R0 + grp + 8)) * C_ + h*HD_ + c;
        *(float2*)&O[offA] = make_float2(o[ni][0]*iA, o[ni][1]*iA);
        *(float2*)&O[offB] = make_float2(o[ni][2]*iB, o[ni][3]*iB);
    }
}

// ======================= launcher ==========================================
extern "C" void kernel_launch(void* const* d_in, const int* in_sizes, int n_in,
                              void* d_out, int out_size)
{
    const float* x     = (const float*)d_in[0];
    const float* Wqkv  = (const float*)d_in[1];
    const float* Wproj = (const float*)d_in[2];
    float* out = (float*)d_out;

    float *qkv, *q, *k, *v, *attn;
    cudaGetSymbolAddress((void**)&qkv,  g_qkv);
    cudaGetSymbolAddress((void**)&q,    g_q);
    cudaGetSymbolAddress((void**)&k,    g_k);
    cudaGetSymbolAddress((void**)&v,    g_v);
    cudaGetSymbolAddress((void**)&attn, g_attn);

    cudaFuncSetAttribute(tf32_gemm,
                         cudaFuncAttributeMaxDynamicSharedMemorySize, GEMM_SMEM);
    cudaFuncSetAttribute(flash_tf32,
                         cudaFuncAttributeMaxDynamicSharedMemorySize, FA_SMEM);

    // 1) qkv = x @ Wqkv
    {
        dim3 grid(QKV_N / GBN, M_ROWS / GBM);
        tf32_gemm<<<grid, 256, GEMM_SMEM>>>(x, Wqkv, qkv, M_ROWS, QKV_N, C_);
    }
    // 2) RoPE + split to [b,h,l,d]
    {
        int total = M_ROWS * NH_ * (HD_/2);
        rope_split_kernel<<<(total + 255) / 256, 256>>>(qkv, q, k, v);
    }
    // 3) causal flash attention (tf32 tensor cores)
    {
        dim3 grid(L_ / 128, B_ * NH_);
        flash_tf32<<<grid, 256, FA_SMEM>>>(q, k, v, attn);
    }
    // 4) out = attn @ Wproj
    {
        dim3 grid(C_ / GBN, M_ROWS / GBM);
        tf32_gemm<<<grid, 256, GEMM_SMEM>>>(attn, Wproj, out, M_ROWS, C_, C_);
    }
}

// round 4
// speedup vs baseline: 3.2521x; 1.0730x over previous
#include <cuda_runtime.h>
#include <cuda_bf16.h>
#include <math.h>
#include <stdint.h>

// Problem constants
#define B_   2
#define L_   2048
#define C_   1024
#define NH_  16
#define HD_  64
#define M_ROWS (B_*L_)          // 4096
#define QKV_N  (3*C_)           // 3072

// -------------------- scratch (static device globals) -----------------------
__device__ float g_qkv  [M_ROWS * QKV_N];
__device__ float g_q    [B_*NH_*L_*HD_];      // [b,h,l,d]  raw fp32
__device__ float g_k    [B_*NH_*L_*HD_];      // tf32-rounded
__device__ float g_v    [B_*NH_*L_*HD_];      // tf32-rounded
__device__ float g_attn [M_ROWS * C_];        // [b,l,h,d]  tf32-rounded
__device__ float g_xr   [M_ROWS * C_];        // x   tf32-rounded
__device__ float g_wqkv [C_ * QKV_N];         // Wqkv tf32-rounded
__device__ float g_wproj[C_ * C_];            // Wproj tf32-rounded

// ======================= small PTX helpers =================================
__device__ __forceinline__ uint32_t f2tf(float x) {
    uint32_t y;
    asm("cvt.rna.tf32.f32 %0, %1;" : "=r"(y) : "f"(x));
    return y;
}
__device__ __forceinline__ float ex2(float x) {
    float y;
    asm("ex2.approx.f32 %0, %1;" : "=f"(y) : "f"(x));
    return y;
}
__device__ __forceinline__ void mma8(float* c,
                                     uint32_t a0, uint32_t a1, uint32_t a2, uint32_t a3,
                                     uint32_t b0, uint32_t b1) {
    asm volatile(
        "mma.sync.aligned.m16n8k8.row.col.f32.tf32.tf32.f32 "
        "{%0,%1,%2,%3}, {%4,%5,%6,%7}, {%8,%9}, {%0,%1,%2,%3};"
        : "+f"(c[0]), "+f"(c[1]), "+f"(c[2]), "+f"(c[3])
        : "r"(a0), "r"(a1), "r"(a2), "r"(a3), "r"(b0), "r"(b1));
}
__device__ __forceinline__ void cpa16(void* smem, const void* gmem) {
    uint32_t s = (uint32_t)__cvta_generic_to_shared(smem);
    asm volatile("cp.async.cg.shared.global [%0], [%1], 16;" :: "r"(s), "l"(gmem));
}
#define CP_COMMIT() asm volatile("cp.async.commit_group;")
#define CP_WAIT0()  asm volatile("cp.async.wait_group 0;")
#define CP_WAIT1()  asm volatile("cp.async.wait_group 1;")

// ======================= tf32 pre-rounding pass ============================
__global__ __launch_bounds__(256)
void round_tf32_kernel(const float4* __restrict__ in, float4* __restrict__ out, int n4)
{
    int i = blockIdx.x * blockDim.x + threadIdx.x;
    if (i >= n4) return;
    float4 v = in[i];
    uint4 u = make_uint4(f2tf(v.x), f2tf(v.y), f2tf(v.z), f2tf(v.w));
    *(uint4*)&out[i] = u;
}

// ======================= TF32 GEMM 128x128x32, 3-stage =====================
// Inputs MUST be pre-rounded to tf32; inner loop is pure LDS+MMA.
#define GBM 128
#define GBN 128
#define GBK 32
#define ASTR 36
#define BSTR 136
#define STW  (GBM*ASTR + GBK*BSTR)     // words per stage: 8960
#define GEMM_SMEM (3 * STW * 4)        // 107520 bytes

__device__ __forceinline__ void gemm_load_tile(
    const float* __restrict__ A, const float* __restrict__ B,
    float* stage, int rowBase, int colBase, int k0, int K, int N, int t)
{
    float* Ad = stage;
    float* Bd = stage + GBM * ASTR;
    #pragma unroll
    for (int i = 0; i < 4; i++) {
        int idx = t + i * 256;
        int r   = idx >> 3;
        int c4  = idx & 7;
        cpa16(&Ad[r * ASTR + c4 * 4], &A[(size_t)(rowBase + r) * K + k0 + c4 * 4]);
    }
    #pragma unroll
    for (int i = 0; i < 4; i++) {
        int idx = t + i * 256;
        int r   = idx >> 5;
        int c4  = idx & 31;
        cpa16(&Bd[r * BSTR + c4 * 4], &B[(size_t)(k0 + r) * N + colBase + c4 * 4]);
    }
}

__global__ __launch_bounds__(256, 2)
void tf32_gemm(const float* __restrict__ A, const float* __restrict__ B,
               float* __restrict__ C, int M, int N, int K)
{
    extern __shared__ float sm[];

    const int t    = threadIdx.x;
    const int lane = t & 31;
    const int warp = t >> 5;
    const int grp  = lane >> 2;
    const int tig  = lane & 3;
    const int wm   = warp >> 2;
    const int wn   = warp & 3;
    const int rowBase = blockIdx.y * GBM;
    const int colBase = blockIdx.x * GBN;

    float acc[4][4][4];
    #pragma unroll
    for (int mi = 0; mi < 4; mi++)
        #pragma unroll
        for (int ni = 0; ni < 4; ni++)
            #pragma unroll
            for (int e = 0; e < 4; e++) acc[mi][ni][e] = 0.f;

    const int NIT = K / GBK;
    gemm_load_tile(A, B, sm,        rowBase, colBase, 0,   K, N, t); CP_COMMIT();
    gemm_load_tile(A, B, sm + STW,  rowBase, colBase, GBK, K, N, t); CP_COMMIT();

    int scur = 0;                       // stage index of iteration `it`
    for (int it = 0; it < NIT; ++it) {
        if (it < NIT - 1) { CP_WAIT1(); } else { CP_WAIT0(); }
        __syncthreads();                // everyone done with stage being re-filled

        if (it + 2 < NIT) {
            int snext = scur + 2; if (snext >= 3) snext -= 3;
            gemm_load_tile(A, B, sm + snext * STW, rowBase, colBase,
                           (it + 2) * GBK, K, N, t);
            CP_COMMIT();
        }

        const uint32_t* Ac = (const uint32_t*)(sm + scur * STW);
        const uint32_t* Bc = Ac + GBM * ASTR;

        #pragma unroll
        for (int ks = 0; ks < 4; ks++) {
            const int k = ks * 8;
            uint32_t af[4][4];
            #pragma unroll
            for (int mi = 0; mi < 4; mi++) {
                int m0 = wm * 64 + mi * 16;
                af[mi][0] = Ac[(m0 + grp    ) * ASTR + k + tig    ];
                af[mi][1] = Ac[(m0 + grp + 8) * ASTR + k + tig    ];
                af[mi][2] = Ac[(m0 + grp    ) * ASTR + k + tig + 4];
                af[mi][3] = Ac[(m0 + grp + 8) * ASTR + k + tig + 4];
            }
            uint32_t bf[4][2];
            #pragma unroll
            for (int ni = 0; ni < 4; ni++) {
                int n0 = wn * 32 + ni * 8;
                bf[ni][0] = Bc[(k + tig    ) * BSTR + n0 + grp];
                bf[ni][1] = Bc[(k + tig + 4) * BSTR + n0 + grp];
            }
            #pragma unroll
            for (int mi = 0; mi < 4; mi++)
                #pragma unroll
                for (int ni = 0; ni < 4; ni++)
                    mma8(acc[mi][ni], af[mi][0], af[mi][1], af[mi][2], af[mi][3],
                         bf[ni][0], bf[ni][1]);
        }
        scur++; if (scur >= 3) scur -= 3;
    }

    #pragma unroll
    for (int mi = 0; mi < 4; mi++) {
        #pragma unroll
        for (int ni = 0; ni < 4; ni++) {
            int row = rowBase + wm * 64 + mi * 16 + grp;
            int col = colBase + wn * 32 + ni * 8 + 2 * tig;
            *(float2*)&C[(size_t)row       * N + col] = make_float2(acc[mi][ni][0], acc[mi][ni][1]);
            *(float2*)&C[(size_t)(row + 8) * N + col] = make_float2(acc[mi][ni][2], acc[mi][ni][3]);
        }
    }
}

// ======================= RoPE + head split =================================
// Writes Q raw fp32; K,V tf32-rounded (rna) so flash skips its convert pass.
__global__ __launch_bounds__(256)
void rope_split_kernel(const float* __restrict__ qkv,
                       float* __restrict__ Q, float* __restrict__ Kd,
                       float* __restrict__ V)
{
    int idx = blockIdx.x * blockDim.x + threadIdx.x;
    const int total = M_ROWS * NH_ * (HD_/2);
    if (idx >= total) return;

    int i  = idx & 31;
    int h  = (idx >> 5) & 15;
    int bl = idx >> 9;
    int b  = bl >> 11;
    int l  = bl & 2047;

    const float* row = qkv + (size_t)bl * QKV_N;
    int d0 = 2*i;

    float qe = row[h*HD_ + d0],          qo = row[h*HD_ + d0 + 1];
    float ke = row[C_   + h*HD_ + d0],   ko = row[C_   + h*HD_ + d0 + 1];
    float ve = row[2*C_ + h*HD_ + d0],   vo = row[2*C_ + h*HD_ + d0 + 1];

    double inv_freq = exp(-((double)d0 / 64.0) * log(10000.0));
    float theta = (float)((double)l * inv_freq);
    float s, c;
    sincosf(theta, &s, &c);

    // reference convention (sin/cos swapped):
    float qe2 = qe*s - qo*c,  qo2 = qe*c + qo*s;
    float ke2 = ke*s - ko*c,  ko2 = ke*c + ko*s;

    size_t o = (((size_t)(b*NH_ + h) * L_) + l) * HD_ + d0;
    Q[o]  = qe2;                      Q[o+1]  = qo2;
    Kd[o] = __uint_as_float(f2tf(ke2)); Kd[o+1] = __uint_as_float(f2tf(ko2));
    V[o]  = __uint_as_float(f2tf(ve));  V[o+1]  = __uint_as_float(f2tf(vo));
}

// ======================= Flash attention (tf32 mma, causal) ================
// Q tile 128 rows, 256 threads = 8 warps. K/V pre-rounded; no convert pass.
#define FKSTR 68
#define FVSTR 72
#define FPSTR 68
#define KS_STAGE (64*FKSTR)
#define VS_STAGE (64*FVSTR)
#define OFF_FV (2*KS_STAGE)
#define OFF_FP (2*KS_STAGE + 2*VS_STAGE)
#define FA_SMEM ((2*KS_STAGE + 2*VS_STAGE + 128*FPSTR) * 4)

__global__ __launch_bounds__(256)
void flash_tf32(const float* __restrict__ Q, const float* __restrict__ K,
                const float* __restrict__ V, float* __restrict__ O)
{
    extern __shared__ float sm[];
    float* Ks = sm;
    float* Vs = sm + OFF_FV;
    float* Ps = sm + OFF_FP;

    const int t    = threadIdx.x;
    const int lane = t & 31;
    const int warp = t >> 5;
    const int grp  = lane >> 2;
    const int tig  = lane & 3;
    const int qt   = (gridDim.x - 1) - blockIdx.x;
    const int bh   = blockIdx.y;
    const size_t base = (size_t)bh * L_ * HD_;
    const int R0 = qt * 128 + warp * 16;

    const float qsc = 0.125f * 1.4426950408889634f;
    uint32_t aq[8][4];
    {
        const float* Qp = Q + base + (size_t)R0 * HD_;
        #pragma unroll
        for (int ks = 0; ks < 8; ks++) {
            int c = 8 * ks + tig;
            aq[ks][0] = f2tf(Qp[(grp    ) * HD_ + c    ] * qsc);
            aq[ks][1] = f2tf(Qp[(grp + 8) * HD_ + c    ] * qsc);
            aq[ks][2] = f2tf(Qp[(grp    ) * HD_ + c + 4] * qsc);
            aq[ks][3] = f2tf(Qp[(grp + 8) * HD_ + c + 4] * qsc);
        }
    }

    float o[8][4];
    #pragma unroll
    for (int ni = 0; ni < 8; ni++)
        #pragma unroll
        for (int e = 0; e < 4; e++) o[ni][e] = 0.f;
    float mA = -1e30f, mB = -1e30f, lA = 0.f, lB = 0.f;

    const int nkt = 2 * qt + 2;

    {
        const float* Kg = K + base;
        const float* Vg = V + base;
        #pragma unroll
        for (int i = 0; i < 4; i++) {
            int idx = t + i * 256;
            int r   = idx >> 4;
            int c4  = idx & 15;
            cpa16(&Ks[r * FKSTR + c4 * 4], &Kg[(size_t)r * HD_ + c4 * 4]);
            cpa16(&Vs[r * FVSTR + c4 * 4], &Vg[(size_t)r * HD_ + c4 * 4]);
        }
        CP_COMMIT();
    }

    for (int kt = 0; kt < nkt; kt++) {
        const int p = kt & 1;
        CP_WAIT0();
        __syncthreads();

        if (kt + 1 < nkt) {
            const float* Kg = K + base + (size_t)(kt + 1) * 64 * HD_;
            const float* Vg = V + base + (size_t)(kt + 1) * 64 * HD_;
            float* Kn = Ks + (p ^ 1) * KS_STAGE;
            float* Vn = Vs + (p ^ 1) * VS_STAGE;
            #pragma unroll
            for (int i = 0; i < 4; i++) {
                int idx = t + i * 256;
                int r   = idx >> 4;
                int c4  = idx & 15;
                cpa16(&Kn[r * FKSTR + c4 * 4], &Kg[(size_t)r * HD_ + c4 * 4]);
                cpa16(&Vn[r * FVSTR + c4 * 4], &Vg[(size_t)r * HD_ + c4 * 4]);
            }
            CP_COMMIT();
        }

        const uint32_t* Kc = (const uint32_t*)(Ks + p * KS_STAGE);
        const uint32_t* Vc = (const uint32_t*)(Vs + p * VS_STAGE);

        const bool active = (kt * 64 <= R0 + 15);
        if (active) {
            float s[8][4];
            #pragma unroll
            for (int ni = 0; ni < 8; ni++)
                #pragma unroll
                for (int e = 0; e < 4; e++) s[ni][e] = 0.f;

            #pragma unroll
            for (int ks = 0; ks < 8; ks++) {
                const int k = ks * 8;
                #pragma unroll
                for (int ni = 0; ni < 8; ni++) {
                    uint32_t b0 = Kc[(ni*8 + grp) * FKSTR + k + tig    ];
                    uint32_t b1 = Kc[(ni*8 + grp) * FKSTR + k + tig + 4];
                    mma8(s[ni], aq[ks][0], aq[ks][1], aq[ks][2], aq[ks][3], b0, b1);
                }
            }

            if (kt * 64 + 63 > R0) {
                #pragma unroll
                for (int ni = 0; ni < 8; ni++)
                    #pragma unroll
                    for (int e = 0; e < 4; e++) {
                        int col = kt*64 + ni*8 + 2*tig + (e & 1);
                        int row = R0 + grp + ((e & 2) ? 8 : 0);
                        if (col > row) s[ni][e] = -1e30f;
                    }
            }

            float mxA = -1e30f, mxB = -1e30f;
            #pragma unroll
            for (int ni = 0; ni < 8; ni++) {
                mxA = fmaxf(mxA, fmaxf(s[ni][0], s[ni][1]));
                mxB = fmaxf(mxB, fmaxf(s[ni][2], s[ni][3]));
            }
            mxA = fmaxf(mxA, __shfl_xor_sync(0xffffffffu, mxA, 1));
            mxA = fmaxf(mxA, __shfl_xor_sync(0xffffffffu, mxA, 2));
            mxB = fmaxf(mxB, __shfl_xor_sync(0xffffffffu, mxB, 1));
            mxB = fmaxf(mxB, __shfl_xor_sync(0xffffffffu, mxB, 2));

            float mnA = fmaxf(mA, mxA), mnB = fmaxf(mB, mxB);
            float aA = ex2(mA - mnA), aB = ex2(mB - mnB);
            float sA = 0.f, sB = 0.f;
            #pragma unroll
            for (int ni = 0; ni < 8; ni++) {
                s[ni][0] = ex2(s[ni][0] - mnA);
                s[ni][1] = ex2(s[ni][1] - mnA);
                s[ni][2] = ex2(s[ni][2] - mnB);
                s[ni][3] = ex2(s[ni][3] - mnB);
                sA += s[ni][0] + s[ni][1];
                sB += s[ni][2] + s[ni][3];
            }
            sA += __shfl_xor_sync(0xffffffffu, sA, 1);
            sA += __shfl_xor_sync(0xffffffffu, sA, 2);
            sB += __shfl_xor_sync(0xffffffffu, sB, 1);
            sB += __shfl_xor_sync(0xffffffffu, sB, 2);
            lA = lA * aA + sA;  lB = lB * aB + sB;
            mA = mnA;           mB = mnB;
            #pragma unroll
            for (int ni = 0; ni < 8; ni++) {
                o[ni][0] *= aA; o[ni][1] *= aA;
                o[ni][2] *= aB; o[ni][3] *= aB;
            }

            float* Pw = Ps + warp * 16 * FPSTR;
            #pragma unroll
            for (int ni = 0; ni < 8; ni++) {
                int c = ni*8 + 2*tig;
                *(uint2*)&Pw[(grp    ) * FPSTR + c] = make_uint2(f2tf(s[ni][0]), f2tf(s[ni][1]));
                *(uint2*)&Pw[(grp + 8) * FPSTR + c] = make_uint2(f2tf(s[ni][2]), f2tf(s[ni][3]));
            }
            __syncwarp();

            const uint32_t* Pu = (const uint32_t*)Pw;
            #pragma unroll
            for (int ks = 0; ks < 8; ks++) {
                const int j = ks * 8;
                uint32_t a0 = Pu[(grp    ) * FPSTR + j + tig    ];
                uint32_t a1 = Pu[(grp + 8) * FPSTR + j + tig    ];
                uint32_t a2 = Pu[(grp    ) * FPSTR + j + tig + 4];
                uint32_t a3 = Pu[(grp + 8) * FPSTR + j + tig + 4];
                #pragma unroll
                for (int ni = 0; ni < 8; ni++) {
                    uint32_t b0 = Vc[(j + tig    ) * FVSTR + ni*8 + grp];
                    uint32_t b1 = Vc[(j + tig + 4) * FVSTR + ni*8 + grp];
                    mma8(o[ni], a0, a1, a2, a3, b0, b1);
                }
            }
        }
    }

    // epilogue: normalize, tf32-round (GEMM2 input), write [b, l, h, d]
    int b = bh >> 4, h = bh & 15;
    float iA = 1.f / lA, iB = 1.f / lB;
    #pragma unroll
    for (int ni = 0; ni < 8; ni++) {
        int c = ni*8 + 2*tig;
        size_t offA = ((size_t)(b*L_ + R0 + grp    )) * C_ + h*HD_ + c;
        size_t offB = ((size_t)(b*L_ + R0 + grp + 8)) * C_ + h*HD_ + c;
        *(uint2*)&O[offA] = make_uint2(f2tf(o[ni][0]*iA), f2tf(o[ni][1]*iA));
        *(uint2*)&O[offB] = make_uint2(f2tf(o[ni][2]*iB), f2tf(o[ni][3]*iB));
    }
}

// ======================= launcher ==========================================
extern "C" void kernel_launch(void* const* d_in, const int* in_sizes, int n_in,
                              void* d_out, int out_size)
{
    const float* x     = (const float*)d_in[0];
    const float* Wqkv  = (const float*)d_in[1];
    const float* Wproj = (const float*)d_in[2];
    float* out = (float*)d_out;

    float *qkv, *q, *k, *v, *attn, *xr, *wqkvr, *wprojr;
    cudaGetSymbolAddress((void**)&qkv,    g_qkv);
    cudaGetSymbolAddress((void**)&q,      g_q);
    cudaGetSymbolAddress((void**)&k,      g_k);
    cudaGetSymbolAddress((void**)&v,      g_v);
    cudaGetSymbolAddress((void**)&attn,   g_attn);
    cudaGetSymbolAddress((void**)&xr,     g_xr);
    cudaGetSymbolAddress((void**)&wqkvr,  g_wqkv);
    cudaGetSymbolAddress((void**)&wprojr, g_wproj);

    cudaFuncSetAttribute(tf32_gemm,
                         cudaFuncAttributeMaxDynamicSharedMemorySize, GEMM_SMEM);
    cudaFuncSetAttribute(flash_tf32,
                         cudaFuncAttributeMaxDynamicSharedMemorySize, FA_SMEM);

    // 0) pre-round GEMM inputs to tf32
    {
        int n4;
        n4 = (M_ROWS * C_) / 4;
        round_tf32_kernel<<<(n4 + 255)/256, 256>>>((const float4*)x, (float4*)xr, n4);
        n4 = (C_ * QKV_N) / 4;
        round_tf32_kernel<<<(n4 + 255)/256, 256>>>((const float4*)Wqkv, (float4*)wqkvr, n4);
        n4 = (C_ * C_) / 4;
        round_tf32_kernel<<<(n4 + 255)/256, 256>>>((const float4*)Wproj, (float4*)wprojr, n4);
    }
    // 1) qkv = x @ Wqkv
    {
        dim3 grid(QKV_N / GBN, M_ROWS / GBM);
        tf32_gemm<<<grid, 256, GEMM_SMEM>>>(xr, wqkvr, qkv, M_ROWS, QKV_N, C_);
    }
    // 2) RoPE + split to [b,h,l,d] (K,V pre-rounded)
    {
        int total = M_ROWS * NH_ * (HD_/2);
        rope_split_kernel<<<(total + 255) / 256, 256>>>(qkv, q, k, v);
    }
    // 3) causal flash attention
    {
        dim3 grid(L_ / 128, B_ * NH_);
        flash_tf32<<<grid, 256, FA_SMEM>>>(q, k, v, attn);
    }
    // 4) out = attn @ Wproj
    {
        dim3 grid(C_ / GBN, M_ROWS / GBM);
        tf32_gemm<<<grid, 256, GEMM_SMEM>>>(attn, wprojr, out, M_ROWS, C_, C_);
    }
}

// round 5
// speedup vs baseline: 3.2986x; 1.0143x over previous
#include <cuda_runtime.h>
#include <cuda_bf16.h>
#include <math.h>
#include <stdint.h>

// Problem constants
#define B_   2
#define L_   2048
#define C_   1024
#define NH_  16
#define HD_  64
#define M_ROWS (B_*L_)          // 4096
#define QKV_N  (3*C_)           // 3072

// -------------------- scratch (static device globals) -----------------------
__device__ float g_qkv  [M_ROWS * QKV_N];
__device__ float g_q    [B_*NH_*L_*HD_];      // [b,h,l,d]  raw fp32
__device__ float g_k    [B_*NH_*L_*HD_];      // tf32-rounded
__device__ float g_v    [B_*NH_*L_*HD_];      // tf32-rounded
__device__ float g_attn [M_ROWS * C_];        // [b,l,h,d]  tf32-rounded
__device__ float g_xr   [M_ROWS * C_];        // x   tf32-rounded
__device__ float g_wqkv [C_ * QKV_N];         // Wqkv tf32-rounded
__device__ float g_wproj[C_ * C_];            // Wproj tf32-rounded

// ======================= small PTX helpers =================================
__device__ __forceinline__ uint32_t f2tf(float x) {
    uint32_t y;
    asm("cvt.rna.tf32.f32 %0, %1;" : "=r"(y) : "f"(x));
    return y;
}
__device__ __forceinline__ float ex2(float x) {
    float y;
    asm("ex2.approx.f32 %0, %1;" : "=f"(y) : "f"(x));
    return y;
}
__device__ __forceinline__ void mma8(float* c,
                                     uint32_t a0, uint32_t a1, uint32_t a2, uint32_t a3,
                                     uint32_t b0, uint32_t b1) {
    asm volatile(
        "mma.sync.aligned.m16n8k8.row.col.f32.tf32.tf32.f32 "
        "{%0,%1,%2,%3}, {%4,%5,%6,%7}, {%8,%9}, {%0,%1,%2,%3};"
        : "+f"(c[0]), "+f"(c[1]), "+f"(c[2]), "+f"(c[3])
        : "r"(a0), "r"(a1), "r"(a2), "r"(a3), "r"(b0), "r"(b1));
}
__device__ __forceinline__ void cpa16(void* smem, const void* gmem) {
    uint32_t s = (uint32_t)__cvta_generic_to_shared(smem);
    asm volatile("cp.async.cg.shared.global [%0], [%1], 16;" :: "r"(s), "l"(gmem));
}
#define CP_COMMIT() asm volatile("cp.async.commit_group;")
#define CP_WAIT0()  asm volatile("cp.async.wait_group 0;")
#define CP_WAIT1()  asm volatile("cp.async.wait_group 1;")

// ======================= tf32 pre-rounding pass ============================
__global__ __launch_bounds__(256)
void round_tf32_kernel(const float4* __restrict__ in, float4* __restrict__ out, int n4)
{
    int i = blockIdx.x * blockDim.x + threadIdx.x;
    if (i >= n4) return;
    float4 v = in[i];
    uint4 u = make_uint4(f2tf(v.x), f2tf(v.y), f2tf(v.z), f2tf(v.w));
    *(uint4*)&out[i] = u;
}

// ======================= TF32 GEMM 128x128x32, 4 warps (64x64 each) ========
// Inputs MUST be pre-rounded to tf32; inner loop is pure LDS+MMA.
// 128 threads; each warp owns a 64x64 output tile -> 32 independent MMAs per
// 8-wide k-step from 24 LDS words (16 FLOP per smem byte).
#define GBM 128
#define GBN 128
#define GBK 32
#define ASTR 36
#define BSTR 136
#define STW  (GBM*ASTR + GBK*BSTR)     // words per stage: 8960
#define GEMM_SMEM (3 * STW * 4)        // 107520 bytes

__device__ __forceinline__ void gemm_load_tile(
    const float* __restrict__ A, const float* __restrict__ B,
    float* stage, int rowBase, int colBase, int k0, int K, int N, int t)
{
    float* Ad = stage;
    float* Bd = stage + GBM * ASTR;
    #pragma unroll
    for (int i = 0; i < 8; i++) {
        int idx = t + i * 128;          // 1024 float4s for A (128x32)
        int r   = idx >> 3;             // 0..127
        int c4  = idx & 7;              // 0..7
        cpa16(&Ad[r * ASTR + c4 * 4], &A[(size_t)(rowBase + r) * K + k0 + c4 * 4]);
    }
    #pragma unroll
    for (int i = 0; i < 8; i++) {
        int idx = t + i * 128;          // 1024 float4s for B (32x128)
        int r   = idx >> 5;             // 0..31
        int c4  = idx & 31;             // 0..31
        cpa16(&Bd[r * BSTR + c4 * 4], &B[(size_t)(k0 + r) * N + colBase + c4 * 4]);
    }
}

__global__ __launch_bounds__(128)
void tf32_gemm(const float* __restrict__ A, const float* __restrict__ B,
               float* __restrict__ C, int M, int N, int K)
{
    extern __shared__ float sm[];

    const int t    = threadIdx.x;
    const int lane = t & 31;
    const int warp = t >> 5;            // 0..3
    const int grp  = lane >> 2;
    const int tig  = lane & 3;
    const int wm   = warp >> 1;         // 0..1 : 64-row half
    const int wn   = warp & 1;          // 0..1 : 64-col half
    const int rowBase = blockIdx.y * GBM;
    const int colBase = blockIdx.x * GBN;

    float acc[4][8][4];                 // mi(16-row frag) x ni(8-col frag)
    #pragma unroll
    for (int mi = 0; mi < 4; mi++)
        #pragma unroll
        for (int ni = 0; ni < 8; ni++)
            #pragma unroll
            for (int e = 0; e < 4; e++) acc[mi][ni][e] = 0.f;

    const int NIT = K / GBK;
    gemm_load_tile(A, B, sm,        rowBase, colBase, 0,   K, N, t); CP_COMMIT();
    gemm_load_tile(A, B, sm + STW,  rowBase, colBase, GBK, K, N, t); CP_COMMIT();

    int scur = 0;
    for (int it = 0; it < NIT; ++it) {
        if (it < NIT - 1) { CP_WAIT1(); } else { CP_WAIT0(); }
        __syncthreads();

        if (it + 2 < NIT) {
            int snext = scur + 2; if (snext >= 3) snext -= 3;
            gemm_load_tile(A, B, sm + snext * STW, rowBase, colBase,
                           (it + 2) * GBK, K, N, t);
            CP_COMMIT();
        }

        const uint32_t* Ac = (const uint32_t*)(sm + scur * STW);
        const uint32_t* Bc = Ac + GBM * ASTR;

        #pragma unroll
        for (int ks = 0; ks < 4; ks++) {
            const int k = ks * 8;
            uint32_t af[4][4];
            #pragma unroll
            for (int mi = 0; mi < 4; mi++) {
                int m0 = wm * 64 + mi * 16;
                af[mi][0] = Ac[(m0 + grp    ) * ASTR + k + tig    ];
                af[mi][1] = Ac[(m0 + grp + 8) * ASTR + k + tig    ];
                af[mi][2] = Ac[(m0 + grp    ) * ASTR + k + tig + 4];
                af[mi][3] = Ac[(m0 + grp + 8) * ASTR + k + tig + 4];
            }
            uint32_t bf[8][2];
            #pragma unroll
            for (int ni = 0; ni < 8; ni++) {
                int n0 = wn * 64 + ni * 8;
                bf[ni][0] = Bc[(k + tig    ) * BSTR + n0 + grp];
                bf[ni][1] = Bc[(k + tig + 4) * BSTR + n0 + grp];
            }
            #pragma unroll
            for (int mi = 0; mi < 4; mi++)
                #pragma unroll
                for (int ni = 0; ni < 8; ni++)
                    mma8(acc[mi][ni], af[mi][0], af[mi][1], af[mi][2], af[mi][3],
                         bf[ni][0], bf[ni][1]);
        }
        scur++; if (scur >= 3) scur -= 3;
    }

    #pragma unroll
    for (int mi = 0; mi < 4; mi++) {
        #pragma unroll
        for (int ni = 0; ni < 8; ni++) {
            int row = rowBase + wm * 64 + mi * 16 + grp;
            int col = colBase + wn * 64 + ni * 8 + 2 * tig;
            *(float2*)&C[(size_t)row       * N + col] = make_float2(acc[mi][ni][0], acc[mi][ni][1]);
            *(float2*)&C[(size_t)(row + 8) * N + col] = make_float2(acc[mi][ni][2], acc[mi][ni][3]);
        }
    }
}

// ======================= RoPE + head split =================================
__global__ __launch_bounds__(256)
void rope_split_kernel(const float* __restrict__ qkv,
                       float* __restrict__ Q, float* __restrict__ Kd,
                       float* __restrict__ V)
{
    int idx = blockIdx.x * blockDim.x + threadIdx.x;
    const int total = M_ROWS * NH_ * (HD_/2);
    if (idx >= total) return;

    int i  = idx & 31;
    int h  = (idx >> 5) & 15;
    int bl = idx >> 9;
    int b  = bl >> 11;
    int l  = bl & 2047;

    const float* row = qkv + (size_t)bl * QKV_N;
    int d0 = 2*i;

    float qe = row[h*HD_ + d0],          qo = row[h*HD_ + d0 + 1];
    float ke = row[C_   + h*HD_ + d0],   ko = row[C_   + h*HD_ + d0 + 1];
    float ve = row[2*C_ + h*HD_ + d0],   vo = row[2*C_ + h*HD_ + d0 + 1];

    double inv_freq = exp(-((double)d0 / 64.0) * log(10000.0));
    float theta = (float)((double)l * inv_freq);
    float s, c;
    sincosf(theta, &s, &c);

    // reference convention (sin/cos swapped):
    float qe2 = qe*s - qo*c,  qo2 = qe*c + qo*s;
    float ke2 = ke*s - ko*c,  ko2 = ke*c + ko*s;

    size_t o = (((size_t)(b*NH_ + h) * L_) + l) * HD_ + d0;
    Q[o]  = qe2;                        Q[o+1]  = qo2;
    Kd[o] = __uint_as_float(f2tf(ke2)); Kd[o+1] = __uint_as_float(f2tf(ko2));
    V[o]  = __uint_as_float(f2tf(ve));  V[o+1]  = __uint_as_float(f2tf(vo));
}

// ======================= Flash attention (tf32 mma, causal) ================
// Q tile 128 rows, 256 threads = 8 warps. K/V pre-rounded; no convert pass.
#define FKSTR 68
#define FVSTR 72
#define FPSTR 68
#define KS_STAGE (64*FKSTR)
#define VS_STAGE (64*FVSTR)
#define OFF_FV (2*KS_STAGE)
#define OFF_FP (2*KS_STAGE + 2*VS_STAGE)
#define FA_SMEM ((2*KS_STAGE + 2*VS_STAGE + 128*FPSTR) * 4)

__global__ __launch_bounds__(256)
void flash_tf32(const float* __restrict__ Q, const float* __restrict__ K,
                const float* __restrict__ V, float* __restrict__ O)
{
    extern __shared__ float sm[];
    float* Ks = sm;
    float* Vs = sm + OFF_FV;
    float* Ps = sm + OFF_FP;

    const int t    = threadIdx.x;
    const int lane = t & 31;
    const int warp = t >> 5;
    const int grp  = lane >> 2;
    const int tig  = lane & 3;
    const int qt   = (gridDim.x - 1) - blockIdx.x;
    const int bh   = blockIdx.y;
    const size_t base = (size_t)bh * L_ * HD_;
    const int R0 = qt * 128 + warp * 16;

    const float qsc = 0.125f * 1.4426950408889634f;
    uint32_t aq[8][4];
    {
        const float* Qp = Q + base + (size_t)R0 * HD_;
        #pragma unroll
        for (int ks = 0; ks < 8; ks++) {
            int c = 8 * ks + tig;
            aq[ks][0] = f2tf(Qp[(grp    ) * HD_ + c    ] * qsc);
            aq[ks][1] = f2tf(Qp[(grp + 8) * HD_ + c    ] * qsc);
            aq[ks][2] = f2tf(Qp[(grp    ) * HD_ + c + 4] * qsc);
            aq[ks][3] = f2tf(Qp[(grp + 8) * HD_ + c + 4] * qsc);
        }
    }

    float o[8][4];
    #pragma unroll
    for (int ni = 0; ni < 8; ni++)
        #pragma unroll
        for (int e = 0; e < 4; e++) o[ni][e] = 0.f;
    float mA = -1e30f, mB = -1e30f, lA = 0.f, lB = 0.f;

    const int nkt = 2 * qt + 2;

    {
        const float* Kg = K + base;
        const float* Vg = V + base;
        #pragma unroll
        for (int i = 0; i < 4; i++) {
            int idx = t + i * 256;
            int r   = idx >> 4;
            int c4  = idx & 15;
            cpa16(&Ks[r * FKSTR + c4 * 4], &Kg[(size_t)r * HD_ + c4 * 4]);
            cpa16(&Vs[r * FVSTR + c4 * 4], &Vg[(size_t)r * HD_ + c4 * 4]);
        }
        CP_COMMIT();
    }

    for (int kt = 0; kt < nkt; kt++) {
        const int p = kt & 1;
        CP_WAIT0();
        __syncthreads();

        if (kt + 1 < nkt) {
            const float* Kg = K + base + (size_t)(kt + 1) * 64 * HD_;
            const float* Vg = V + base + (size_t)(kt + 1) * 64 * HD_;
            float* Kn = Ks + (p ^ 1) * KS_STAGE;
            float* Vn = Vs + (p ^ 1) * VS_STAGE;
            #pragma unroll
            for (int i = 0; i < 4; i++) {
                int idx = t + i * 256;
                int r   = idx >> 4;
                int c4  = idx & 15;
                cpa16(&Kn[r * FKSTR + c4 * 4], &Kg[(size_t)r * HD_ + c4 * 4]);
                cpa16(&Vn[r * FVSTR + c4 * 4], &Vg[(size_t)r * HD_ + c4 * 4]);
            }
            CP_COMMIT();
        }

        const uint32_t* Kc = (const uint32_t*)(Ks + p * KS_STAGE);
        const uint32_t* Vc = (const uint32_t*)(Vs + p * VS_STAGE);

        const bool active = (kt * 64 <= R0 + 15);
        if (active) {
            float s[8][4];
            #pragma unroll
            for (int ni = 0; ni < 8; ni++)
                #pragma unroll
                for (int e = 0; e < 4; e++) s[ni][e] = 0.f;

            #pragma unroll
            for (int ks = 0; ks < 8; ks++) {
                const int k = ks * 8;
                #pragma unroll
                for (int ni = 0; ni < 8; ni++) {
                    uint32_t b0 = Kc[(ni*8 + grp) * FKSTR + k + tig    ];
                    uint32_t b1 = Kc[(ni*8 + grp) * FKSTR + k + tig + 4];
                    mma8(s[ni], aq[ks][0], aq[ks][1], aq[ks][2], aq[ks][3], b0, b1);
                }
            }

            if (kt * 64 + 63 > R0) {
                #pragma unroll
                for (int ni = 0; ni < 8; ni++)
                    #pragma unroll
                    for (int e = 0; e < 4; e++) {
                        int col = kt*64 + ni*8 + 2*tig + (e & 1);
                        int row = R0 + grp + ((e & 2) ? 8 : 0);
                        if (col > row) s[ni][e] = -1e30f;
                    }
            }

            float mxA = -1e30f, mxB = -1e30f;
            #pragma unroll
            for (int ni = 0; ni < 8; ni++) {
                mxA = fmaxf(mxA, fmaxf(s[ni][0], s[ni][1]));
                mxB = fmaxf(mxB, fmaxf(s[ni][2], s[ni][3]));
            }
            mxA = fmaxf(mxA, __shfl_xor_sync(0xffffffffu, mxA, 1));
            mxA = fmaxf(mxA, __shfl_xor_sync(0xffffffffu, mxA, 2));
            mxB = fmaxf(mxB, __shfl_xor_sync(0xffffffffu, mxB, 1));
            mxB = fmaxf(mxB, __shfl_xor_sync(0xffffffffu, mxB, 2));

            float mnA = fmaxf(mA, mxA), mnB = fmaxf(mB, mxB);
            float aA = ex2(mA - mnA), aB = ex2(mB - mnB);
            float sA = 0.f, sB = 0.f;
            #pragma unroll
            for (int ni = 0; ni < 8; ni++) {
                s[ni][0] = ex2(s[ni][0] - mnA);
                s[ni][1] = ex2(s[ni][1] - mnA);
                s[ni][2] = ex2(s[ni][2] - mnB);
                s[ni][3] = ex2(s[ni][3] - mnB);
                sA += s[ni][0] + s[ni][1];
                sB += s[ni][2] + s[ni][3];
            }
            sA += __shfl_xor_sync(0xffffffffu, sA, 1);
            sA += __shfl_xor_sync(0xffffffffu, sA, 2);
            sB += __shfl_xor_sync(0xffffffffu, sB, 1);
            sB += __shfl_xor_sync(0xffffffffu, sB, 2);
            lA = lA * aA + sA;  lB = lB * aB + sB;
            mA = mnA;           mB = mnB;
            #pragma unroll
            for (int ni = 0; ni < 8; ni++) {
                o[ni][0] *= aA; o[ni][1] *= aA;
                o[ni][2] *= aB; o[ni][3] *= aB;
            }

            float* Pw = Ps + warp * 16 * FPSTR;
            #pragma unroll
            for (int ni = 0; ni < 8; ni++) {
                int c = ni*8 + 2*tig;
                *(uint2*)&Pw[(grp    ) * FPSTR + c] = make_uint2(f2tf(s[ni][0]), f2tf(s[ni][1]));
                *(uint2*)&Pw[(grp + 8) * FPSTR + c] = make_uint2(f2tf(s[ni][2]), f2tf(s[ni][3]));
            }
            __syncwarp();

            const uint32_t* Pu = (const uint32_t*)Pw;
            #pragma unroll
            for (int ks = 0; ks < 8; ks++) {
                const int j = ks * 8;
                uint32_t a0 = Pu[(grp    ) * FPSTR + j + tig    ];
                uint32_t a1 = Pu[(grp + 8) * FPSTR + j + tig    ];
                uint32_t a2 = Pu[(grp    ) * FPSTR + j + tig + 4];
                uint32_t a3 = Pu[(grp + 8) * FPSTR + j + tig + 4];
                #pragma unroll
                for (int ni = 0; ni < 8; ni++) {
                    uint32_t b0 = Vc[(j + tig    ) * FVSTR + ni*8 + grp];
                    uint32_t b1 = Vc[(j + tig + 4) * FVSTR + ni*8 + grp];
                    mma8(o[ni], a0, a1, a2, a3, b0, b1);
                }
            }
        }
    }

    // epilogue: normalize, tf32-round (GEMM2 input), write [b, l, h, d]
    int b = bh >> 4, h = bh & 15;
    float iA = 1.f / lA, iB = 1.f / lB;
    #pragma unroll
    for (int ni = 0; ni < 8; ni++) {
        int c = ni*8 + 2*tig;
        size_t offA = ((size_t)(b*L_ + R0 + grp    )) * C_ + h*HD_ + c;
        size_t offB = ((size_t)(b*L_ + R0 + grp + 8)) * C_ + h*HD_ + c;
        *(uint2*)&O[offA] = make_uint2(f2tf(o[ni][0]*iA), f2tf(o[ni][1]*iA));
        *(uint2*)&O[offB] = make_uint2(f2tf(o[ni][2]*iB), f2tf(o[ni][3]*iB));
    }
}

// ======================= launcher ==========================================
extern "C" void kernel_launch(void* const* d_in, const int* in_sizes, int n_in,
                              void* d_out, int out_size)
{
    const float* x     = (const float*)d_in[0];
    const float* Wqkv  = (const float*)d_in[1];
    const float* Wproj = (const float*)d_in[2];
    float* out = (float*)d_out;

    float *qkv, *q, *k, *v, *attn, *xr, *wqkvr, *wprojr;
    cudaGetSymbolAddress((void**)&qkv,    g_qkv);
    cudaGetSymbolAddress((void**)&q,      g_q);
    cudaGetSymbolAddress((void**)&k,      g_k);
    cudaGetSymbolAddress((void**)&v,      g_v);
    cudaGetSymbolAddress((void**)&attn,   g_attn);
    cudaGetSymbolAddress((void**)&xr,     g_xr);
    cudaGetSymbolAddress((void**)&wqkvr,  g_wqkv);
    cudaGetSymbolAddress((void**)&wprojr, g_wproj);

    cudaFuncSetAttribute(tf32_gemm,
                         cudaFuncAttributeMaxDynamicSharedMemorySize, GEMM_SMEM);
    cudaFuncSetAttribute(flash_tf32,
                         cudaFuncAttributeMaxDynamicSharedMemorySize, FA_SMEM);

    // 0) pre-round GEMM inputs to tf32
    {
        int n4;
        n4 = (M_ROWS * C_) / 4;
        round_tf32_kernel<<<(n4 + 255)/256, 256>>>((const float4*)x, (float4*)xr, n4);
        n4 = (C_ * QKV_N) / 4;
        round_tf32_kernel<<<(n4 + 255)/256, 256>>>((const float4*)Wqkv, (float4*)wqkvr, n4);
        n4 = (C_ * C_) / 4;
        round_tf32_kernel<<<(n4 + 255)/256, 256>>>((const float4*)Wproj, (float4*)wprojr, n4);
    }
    // 1) qkv = x @ Wqkv
    {
        dim3 grid(QKV_N / GBN, M_ROWS / GBM);
        tf32_gemm<<<grid, 128, GEMM_SMEM>>>(xr, wqkvr, qkv, M_ROWS, QKV_N, C_);
    }
    // 2) RoPE + split to [b,h,l,d] (K,V pre-rounded)
    {
        int total = M_ROWS * NH_ * (HD_/2);
        rope_split_kernel<<<(total + 255) / 256, 256>>>(qkv, q, k, v);
    }
    // 3) causal flash attention
    {
        dim3 grid(L_ / 128, B_ * NH_);
        flash_tf32<<<grid, 256, FA_SMEM>>>(q, k, v, attn);
    }
    // 4) out = attn @ Wproj
    {
        dim3 grid(C_ / GBN, M_ROWS / GBM);
        tf32_gemm<<<grid, 128, GEMM_SMEM>>>(attn, wprojr, out, M_ROWS, C_, C_);
    }
}

// round 7
// speedup vs baseline: 5.3641x; 1.6262x over previous
#include <cuda_runtime.h>
#include <cuda_fp16.h>
#include <math.h>
#include <stdint.h>

// Problem constants
#define B_   2
#define L_   2048
#define C_   1024
#define NH_  16
#define HD_  64
#define M_ROWS (B_*L_)          // 4096
#define QKV_N  (3*C_)           // 3072

// -------------------- scratch (static device globals) -----------------------
__device__ float  g_qkv [M_ROWS * QKV_N];     // fp32
__device__ float  g_q   [B_*NH_*L_*HD_];      // [b,h,l,d] fp32
__device__ __half g_kh  [B_*NH_*L_*HD_];      // [b,h,l,d] fp16
__device__ __half g_vh  [B_*NH_*L_*HD_];      // [b,h,l,d] fp16
__device__ __half g_vt  [B_*NH_*HD_*L_];      // [b,h,d,l] fp16 (transposed V)
__device__ __half g_xh  [M_ROWS * C_];        // x fp16 [M,K]
__device__ __half g_wq  [QKV_N * C_];         // Wqkv^T fp16 [N,K]
__device__ __half g_wp  [C_ * C_];            // Wproj^T fp16 [N,K]
__device__ __half g_ah  [M_ROWS * C_];        // attn fp16 [b,l,h,d] == [M,C]

// ======================= small helpers =====================================
__device__ __forceinline__ float ex2(float x) {
    float y; asm("ex2.approx.f32 %0, %1;" : "=f"(y) : "f"(x)); return y;
}
__device__ __forceinline__ uint32_t pack2(float a, float b) {
    __half2 h = __floats2half2_rn(a, b);
    return *(uint32_t*)&h;
}
// fp16 mma: D[16,8] += A[16,16] * B[16,8], row.col, f32 accum
__device__ __forceinline__ void mma16(float* c,
                                      uint32_t a0, uint32_t a1, uint32_t a2, uint32_t a3,
                                      uint32_t b0, uint32_t b1) {
    asm volatile(
        "mma.sync.aligned.m16n8k16.row.col.f32.f16.f16.f32 "
        "{%0,%1,%2,%3}, {%4,%5,%6,%7}, {%8,%9}, {%0,%1,%2,%3};"
        : "+f"(c[0]), "+f"(c[1]), "+f"(c[2]), "+f"(c[3])
        : "r"(a0), "r"(a1), "r"(a2), "r"(a3), "r"(b0), "r"(b1));
}
__device__ __forceinline__ void cpa16(void* smem, const void* gmem) {
    uint32_t s = (uint32_t)__cvta_generic_to_shared(smem);
    asm volatile("cp.async.cg.shared.global [%0], [%1], 16;" :: "r"(s), "l"(gmem));
}
#define CP_COMMIT() asm volatile("cp.async.commit_group;")
#define CP_WAIT0()  asm volatile("cp.async.wait_group 0;")
#define CP_WAIT1()  asm volatile("cp.async.wait_group 1;")

// ======================= prepass kernels ===================================
// fp32 -> fp16 (vectorized)
__global__ __launch_bounds__(256)
void cvt_half_kernel(const float4* __restrict__ in, uint2* __restrict__ out, int n4)
{
    int i = blockIdx.x * blockDim.x + threadIdx.x;
    if (i >= n4) return;
    float4 v = in[i];
    out[i] = make_uint2(pack2(v.x, v.y), pack2(v.z, v.w));
}

// fp32 [R, Ccols] -> fp16 [Ccols, R]
__global__ __launch_bounds__(256)
void transpose_half_kernel(const float* __restrict__ in, __half* __restrict__ out,
                           int R, int Ccols)
{
    __shared__ float tile[32][33];
    int tx = threadIdx.x & 31, ty = threadIdx.x >> 5;
    int c0 = blockIdx.x * 32, r0 = blockIdx.y * 32;
    #pragma unroll
    for (int j = ty; j < 32; j += 8)
        tile[j][tx] = in[(size_t)(r0 + j) * Ccols + c0 + tx];
    __syncthreads();
    #pragma unroll
    for (int j = ty; j < 32; j += 8)
        out[(size_t)(c0 + j) * R + r0 + tx] = __float2half(tile[tx][j]);
}

// V [bh][l][d] -> VT [bh][d][l]  (64x64 half tiles)
__global__ __launch_bounds__(256)
void vtrans_kernel(const __half* __restrict__ V, __half* __restrict__ VT)
{
    __shared__ __half tl[64][65];
    int bh = blockIdx.y;
    int l0 = blockIdx.x * 64;
    int tx = threadIdx.x & 63, ty = threadIdx.x >> 6;
    const __half* Vp = V + (size_t)bh * L_ * HD_;
    __half* Tp = VT + (size_t)bh * HD_ * L_;
    #pragma unroll
    for (int j = ty; j < 64; j += 4)
        tl[j][tx] = Vp[(size_t)(l0 + j) * HD_ + tx];
    __syncthreads();
    #pragma unroll
    for (int j = ty; j < 64; j += 4)
        Tp[(size_t)j * L_ + l0 + tx] = tl[tx][j];
}

// ======================= FP16 GEMM 128x128x32, 4 warps (64x64) =============
// C[M,N] fp32 = A[M,K] fp16 row-major x B[N,K] fp16 (used as col-major B^T).
#define GBK 32
#define RSTR 20                         // words (uint32) per smem row (40 halves)
#define TSTW (128 * RSTR)               // words per operand tile: 2560
#define STW  (2 * TSTW)                 // words per stage: 5120 (20 KB)
#define GEMM_SMEM (3 * STW * 4)         // 61,440 B

__device__ __forceinline__ void gemm_load_tile(
    const __half* __restrict__ A, const __half* __restrict__ B,
    uint32_t* stage, int rowBase, int colBase, int k0, int K, int t)
{
    #pragma unroll
    for (int i = 0; i < 4; i++) {
        int idx = t + i * 128;          // 512 chunks of 16B for A (128x32 halves)
        int r = idx >> 2, c = idx & 3;
        cpa16(stage + r * RSTR + c * 4, A + (size_t)(rowBase + r) * K + k0 + c * 8);
    }
    #pragma unroll
    for (int i = 0; i < 4; i++) {
        int idx = t + i * 128;
        int r = idx >> 2, c = idx & 3;
        cpa16(stage + TSTW + r * RSTR + c * 4,
              B + (size_t)(colBase + r) * K + k0 + c * 8);
    }
}

__global__ __launch_bounds__(128)
void gemm_fp16(const __half* __restrict__ A, const __half* __restrict__ B,
               float* __restrict__ C, int M, int N, int K)
{
    extern __shared__ uint32_t smw[];

    const int t    = threadIdx.x;
    const int lane = t & 31;
    const int warp = t >> 5;            // 0..3
    const int grp  = lane >> 2;
    const int tig  = lane & 3;
    const int wm   = warp >> 1;         // 0..1
    const int wn   = warp & 1;          // 0..1
    const int rowBase = blockIdx.y * 128;
    const int colBase = blockIdx.x * 128;

    float acc[4][8][4];
    #pragma unroll
    for (int mi = 0; mi < 4; mi++)
        #pragma unroll
        for (int ni = 0; ni < 8; ni++)
            #pragma unroll
            for (int e = 0; e < 4; e++) acc[mi][ni][e] = 0.f;

    const int NIT = K / GBK;
    gemm_load_tile(A, B, smw,       rowBase, colBase, 0,   K, t); CP_COMMIT();
    gemm_load_tile(A, B, smw + STW, rowBase, colBase, GBK, K, t); CP_COMMIT();

    int scur = 0;
    for (int it = 0; it < NIT; ++it) {
        if (it < NIT - 1) { CP_WAIT1(); } else { CP_WAIT0(); }
        __syncthreads();

        if (it + 2 < NIT) {
            int snext = scur + 2; if (snext >= 3) snext -= 3;
            gemm_load_tile(A, B, smw + snext * STW, rowBase, colBase,
                           (it + 2) * GBK, K, t);
            CP_COMMIT();
        }

        const uint32_t* Ac = smw + scur * STW;
        const uint32_t* Bc = Ac + TSTW;

        #pragma unroll
        for (int ks = 0; ks < 2; ks++) {        // 2 k-steps of 16
            const int kw = ks * 8;              // word offset within row
            uint32_t af[4][4];
            #pragma unroll
            for (int mi = 0; mi < 4; mi++) {
                int m0 = wm * 64 + mi * 16;
                af[mi][0] = Ac[(m0 + grp    ) * RSTR + kw + tig    ];
                af[mi][1] = Ac[(m0 + grp + 8) * RSTR + kw + tig    ];
                af[mi][2] = Ac[(m0 + grp    ) * RSTR + kw + tig + 4];
                af[mi][3] = Ac[(m0 + grp + 8) * RSTR + kw + tig + 4];
            }
            uint32_t bf[8][2];
            #pragma unroll
            for (int ni = 0; ni < 8; ni++) {
                int n0 = wn * 64 + ni * 8;
                bf[ni][0] = Bc[(n0 + grp) * RSTR + kw + tig    ];
                bf[ni][1] = Bc[(n0 + grp) * RSTR + kw + tig + 4];
            }
            #pragma unroll
            for (int mi = 0; mi < 4; mi++)
                #pragma unroll
                for (int ni = 0; ni < 8; ni++)
                    mma16(acc[mi][ni], af[mi][0], af[mi][1], af[mi][2], af[mi][3],
                          bf[ni][0], bf[ni][1]);
        }
        scur++; if (scur >= 3) scur -= 3;
    }

    #pragma unroll
    for (int mi = 0; mi < 4; mi++) {
        #pragma unroll
        for (int ni = 0; ni < 8; ni++) {
            int row = rowBase + wm * 64 + mi * 16 + grp;
            int col = colBase + wn * 64 + ni * 8 + 2 * tig;
            *(float2*)&C[(size_t)row       * N + col] = make_float2(acc[mi][ni][0], acc[mi][ni][1]);
            *(float2*)&C[(size_t)(row + 8) * N + col] = make_float2(acc[mi][ni][2], acc[mi][ni][3]);
        }
    }
}

// ======================= RoPE + head split =================================
// Q fp32 [b,h,l,d]; K,V fp16 [b,h,l,d].
__global__ __launch_bounds__(256)
void rope_split_kernel(const float* __restrict__ qkv,
                       float* __restrict__ Q, __half* __restrict__ Kh,
                       __half* __restrict__ Vh)
{
    int idx = blockIdx.x * blockDim.x + threadIdx.x;
    const int total = M_ROWS * NH_ * (HD_/2);
    if (idx >= total) return;

    int i  = idx & 31;
    int h  = (idx >> 5) & 15;
    int bl = idx >> 9;
    int b  = bl >> 11;
    int l  = bl & 2047;

    const float* row = qkv + (size_t)bl * QKV_N;
    int d0 = 2*i;

    float qe = row[h*HD_ + d0],          qo = row[h*HD_ + d0 + 1];
    float ke = row[C_   + h*HD_ + d0],   ko = row[C_   + h*HD_ + d0 + 1];
    float ve = row[2*C_ + h*HD_ + d0],   vo = row[2*C_ + h*HD_ + d0 + 1];

    double inv_freq = exp(-((double)d0 / 64.0) * log(10000.0));
    float theta = (float)((double)l * inv_freq);
    float s, c;
    sincosf(theta, &s, &c);

    // reference convention (sin/cos swapped):
    float qe2 = qe*s - qo*c,  qo2 = qe*c + qo*s;
    float ke2 = ke*s - ko*c,  ko2 = ke*c + ko*s;

    size_t o = (((size_t)(b*NH_ + h) * L_) + l) * HD_ + d0;
    Q[o] = qe2;  Q[o+1] = qo2;
    *(__half2*)&Kh[o] = __floats2half2_rn(ke2, ko2);
    *(__half2*)&Vh[o] = __floats2half2_rn(ve, vo);
}

// ======================= Flash attention (fp16 mma, causal) ================
// Q tile 128 rows, 256 threads = 8 warps, warp owns 16 rows. K/VT double-buffered.
#define FSTR 36                         // words per smem row (72 halves)
#define KT_W (64 * FSTR)                // words per K or VT stage: 2304
#define OFF_VT (2 * KT_W)
#define OFF_P  (4 * KT_W)
#define PW_W (16 * FSTR)                // words per warp P region: 576
#define FA_SMEM ((4 * KT_W + 8 * PW_W) * 4)   // 55,296 B

__global__ __launch_bounds__(256)
void flash_fp16(const float* __restrict__ Q, const __half* __restrict__ K,
                const __half* __restrict__ VT, __half* __restrict__ O)
{
    extern __shared__ uint32_t smw[];
    uint32_t* Ksm = smw;                 // [2][64][FSTR]
    uint32_t* Vsm = smw + OFF_VT;        // [2][64][FSTR]  (VT: rows=d, cols=j)
    uint32_t* Psm = smw + OFF_P;         // [8][16][FSTR]

    const int t    = threadIdx.x;
    const int lane = t & 31;
    const int warp = t >> 5;
    const int grp  = lane >> 2;
    const int tig  = lane & 3;
    const int qt   = (gridDim.x - 1) - blockIdx.x;   // heavy tiles first
    const int bh   = blockIdx.y;
    const size_t base = (size_t)bh * L_ * HD_;
    const int R0 = qt * 128 + warp * 16;

    // Q fragments (scale*log2e folded), packed fp16
    const float qsc = 0.125f * 1.4426950408889634f;
    uint32_t aq[4][4];
    {
        const float* Qp = Q + base + (size_t)R0 * HD_;
        #pragma unroll
        for (int ks = 0; ks < 4; ks++) {
            int c = 16 * ks + 2 * tig;
            aq[ks][0] = pack2(Qp[(grp    ) * HD_ + c    ] * qsc, Qp[(grp    ) * HD_ + c + 1] * qsc);
            aq[ks][1] = pack2(Qp[(grp + 8) * HD_ + c    ] * qsc, Qp[(grp + 8) * HD_ + c + 1] * qsc);
            aq[ks][2] = pack2(Qp[(grp    ) * HD_ + c + 8] * qsc, Qp[(grp    ) * HD_ + c + 9] * qsc);
            aq[ks][3] = pack2(Qp[(grp + 8) * HD_ + c + 8] * qsc, Qp[(grp + 8) * HD_ + c + 9] * qsc);
        }
    }

    float o[8][4];
    #pragma unroll
    for (int ni = 0; ni < 8; ni++)
        #pragma unroll
        for (int e = 0; e < 4; e++) o[ni][e] = 0.f;
    float mA = -1e30f, mB = -1e30f, lA = 0.f, lB = 0.f;

    const int nkt = 2 * qt + 2;

    // prologue: stage 0 (K rows: key l; VT rows: d — both 64x64 halves)
    {
        const __half* Kg = K + base;
        const __half* Vg = VT + (size_t)bh * HD_ * L_;
        #pragma unroll
        for (int i = 0; i < 2; i++) {
            int idx = t + i * 256;      // 512 chunks
            int r = idx >> 3, c = idx & 7;
            cpa16(Ksm + r * FSTR + c * 4, Kg + (size_t)r * HD_ + c * 8);
            cpa16(Vsm + r * FSTR + c * 4, Vg + (size_t)r * L_ + c * 8);
        }
        CP_COMMIT();
    }

    for (int kt = 0; kt < nkt; kt++) {
        const int p = kt & 1;
        CP_WAIT0();
        __syncthreads();

        if (kt + 1 < nkt) {
            const __half* Kg = K + base + (size_t)(kt + 1) * 64 * HD_;
            const __half* Vg = VT + (size_t)bh * HD_ * L_ + (size_t)(kt + 1) * 64;
            uint32_t* Kn = Ksm + (p ^ 1) * KT_W;
            uint32_t* Vn = Vsm + (p ^ 1) * KT_W;
            #pragma unroll
            for (int i = 0; i < 2; i++) {
                int idx = t + i * 256;
                int r = idx >> 3, c = idx & 7;
                cpa16(Kn + r * FSTR + c * 4, Kg + (size_t)r * HD_ + c * 8);
                cpa16(Vn + r * FSTR + c * 4, Vg + (size_t)r * L_ + c * 8);
            }
            CP_COMMIT();
        }

        const uint32_t* Kc = Ksm + p * KT_W;
        const uint32_t* Vc = Vsm + p * KT_W;

        const bool active = (kt * 64 <= R0 + 15);
        if (active) {
            // ---- S = Q K^T (16 x 64 per warp), 4 k-steps of 16 ----
            float s[8][4];
            #pragma unroll
            for (int ni = 0; ni < 8; ni++)
                #pragma unroll
                for (int e = 0; e < 4; e++) s[ni][e] = 0.f;

            #pragma unroll
            for (int ks = 0; ks < 4; ks++) {
                const int kw = ks * 8;
                #pragma unroll
                for (int ni = 0; ni < 8; ni++) {
                    uint32_t b0 = Kc[(ni*8 + grp) * FSTR + kw + tig    ];
                    uint32_t b1 = Kc[(ni*8 + grp) * FSTR + kw + tig + 4];
                    mma16(s[ni], aq[ks][0], aq[ks][1], aq[ks][2], aq[ks][3], b0, b1);
                }
            }

            // causal mask near the diagonal
            if (kt * 64 + 63 > R0) {
                #pragma unroll
                for (int ni = 0; ni < 8; ni++)
                    #pragma unroll
                    for (int e = 0; e < 4; e++) {
                        int col = kt*64 + ni*8 + 2*tig + (e & 1);
                        int row = R0 + grp + ((e & 2) ? 8 : 0);
                        if (col > row) s[ni][e] = -1e30f;
                    }
            }

            // ---- online softmax (exp2 domain) ----
            float mxA = -1e30f, mxB = -1e30f;
            #pragma unroll
            for (int ni = 0; ni < 8; ni++) {
                mxA = fmaxf(mxA, fmaxf(s[ni][0], s[ni][1]));
                mxB = fmaxf(mxB, fmaxf(s[ni][2], s[ni][3]));
            }
            mxA = fmaxf(mxA, __shfl_xor_sync(0xffffffffu, mxA, 1));
            mxA = fmaxf(mxA, __shfl_xor_sync(0xffffffffu, mxA, 2));
            mxB = fmaxf(mxB, __shfl_xor_sync(0xffffffffu, mxB, 1));
            mxB = fmaxf(mxB, __shfl_xor_sync(0xffffffffu, mxB, 2));

            float mnA = fmaxf(mA, mxA), mnB = fmaxf(mB, mxB);
            float aA = ex2(mA - mnA), aB = ex2(mB - mnB);
            float sA = 0.f, sB = 0.f;
            #pragma unroll
            for (int ni = 0; ni < 8; ni++) {
                s[ni][0] = ex2(s[ni][0] - mnA);
                s[ni][1] = ex2(s[ni][1] - mnA);
                s[ni][2] = ex2(s[ni][2] - mnB);
                s[ni][3] = ex2(s[ni][3] - mnB);
                sA += s[ni][0] + s[ni][1];
                sB += s[ni][2] + s[ni][3];
            }
            sA += __shfl_xor_sync(0xffffffffu, sA, 1);
            sA += __shfl_xor_sync(0xffffffffu, sA, 2);
            sB += __shfl_xor_sync(0xffffffffu, sB, 1);
            sB += __shfl_xor_sync(0xffffffffu, sB, 2);
            lA = lA * aA + sA;  lB = lB * aB + sB;
            mA = mnA;           mB = mnB;
            #pragma unroll
            for (int ni = 0; ni < 8; ni++) {
                o[ni][0] *= aA; o[ni][1] *= aA;
                o[ni][2] *= aB; o[ni][3] *= aB;
            }

            // ---- stage P (fp16, per-warp region) ----
            uint32_t* Pw = Psm + warp * PW_W;
            #pragma unroll
            for (int ni = 0; ni < 8; ni++) {
                Pw[(grp    ) * FSTR + ni * 4 + tig] = pack2(s[ni][0], s[ni][1]);
                Pw[(grp + 8) * FSTR + ni * 4 + tig] = pack2(s[ni][2], s[ni][3]);
            }
            __syncwarp();

            // ---- O += P V : A = P[16,64], B = V (VT rows=d) ----
            #pragma unroll
            for (int ks = 0; ks < 4; ks++) {
                const int kw = ks * 8;
                uint32_t a0 = Pw[(grp    ) * FSTR + kw + tig    ];
                uint32_t a1 = Pw[(grp + 8) * FSTR + kw + tig    ];
                uint32_t a2 = Pw[(grp    ) * FSTR + kw + tig + 4];
                uint32_t a3 = Pw[(grp + 8) * FSTR + kw + tig + 4];
                #pragma unroll
                for (int ni = 0; ni < 8; ni++) {
                    uint32_t b0 = Vc[(ni*8 + grp) * FSTR + kw + tig    ];
                    uint32_t b1 = Vc[(ni*8 + grp) * FSTR + kw + tig + 4];
                    mma16(o[ni], a0, a1, a2, a3, b0, b1);
                }
            }
        }
    }

    // epilogue: normalize, write attn fp16 [b, l, h, d] (= GEMM2's A)
    int b = bh >> 4, h = bh & 15;
    float iA = 1.f / lA, iB = 1.f / lB;
    #pragma unroll
    for (int ni = 0; ni < 8; ni++) {
        int c = ni*8 + 2*tig;
        size_t offA = ((size_t)(b*L_ + R0 + grp    )) * C_ + h*HD_ + c;
        size_t offB = ((size_t)(b*L_ + R0 + grp + 8)) * C_ + h*HD_ + c;
        *(uint32_t*)&O[offA] = pack2(o[ni][0]*iA, o[ni][1]*iA);
        *(uint32_t*)&O[offB] = pack2(o[ni][2]*iB, o[ni][3]*iB);
    }
}

// ======================= launcher ==========================================
extern "C" void kernel_launch(void* const* d_in, const int* in_sizes, int n_in,
                              void* d_out, int out_size)
{
    const float* x     = (const float*)d_in[0];
    const float* Wqkv  = (const float*)d_in[1];
    const float* Wproj = (const float*)d_in[2];
    float* out = (float*)d_out;

    float *qkv, *q;
    __half *kh, *vh, *vt, *xh, *wq, *wp, *ah;
    cudaGetSymbolAddress((void**)&qkv, g_qkv);
    cudaGetSymbolAddress((void**)&q,   g_q);
    cudaGetSymbolAddress((void**)&kh,  g_kh);
    cudaGetSymbolAddress((void**)&vh,  g_vh);
    cudaGetSymbolAddress((void**)&vt,  g_vt);
    cudaGetSymbolAddress((void**)&xh,  g_xh);
    cudaGetSymbolAddress((void**)&wq,  g_wq);
    cudaGetSymbolAddress((void**)&wp,  g_wp);
    cudaGetSymbolAddress((void**)&ah,  g_ah);

    cudaFuncSetAttribute(gemm_fp16,
                         cudaFuncAttributeMaxDynamicSharedMemorySize, GEMM_SMEM);
    cudaFuncSetAttribute(flash_fp16,
                         cudaFuncAttributeMaxDynamicSharedMemorySize, FA_SMEM);

    // 0) convert x to fp16; transpose weights to [N,K] fp16
    {
        int n4 = (M_ROWS * C_) / 4;
        cvt_half_kernel<<<(n4 + 255)/256, 256>>>((const float4*)x, (uint2*)xh, n4);
        transpose_half_kernel<<<dim3(QKV_N/32, C_/32), 256>>>(Wqkv, wq, C_, QKV_N);
        transpose_half_kernel<<<dim3(C_/32,   C_/32), 256>>>(Wproj, wp, C_, C_);
    }
    // 1) qkv = x @ Wqkv  (fp16 mma, fp32 accum/out)
    gemm_fp16<<<dim3(QKV_N/128, M_ROWS/128), 128, GEMM_SMEM>>>(
        xh, wq, qkv, M_ROWS, QKV_N, C_);
    // 2) RoPE + head split (Q fp32; K,V fp16)
    {
        int total = M_ROWS * NH_ * (HD_/2);
        rope_split_kernel<<<(total + 255) / 256, 256>>>(qkv, q, kh, vh);
    }
    // 2b) V transpose -> [b,h,d,l]
    vtrans_kernel<<<dim3(L_/64, B_*NH_), 256>>>(vh, vt);
    // 3) causal flash attention (fp16 mma) -> attn fp16
    {
        dim3 grid(L_ / 128, B_ * NH_);
        flash_fp16<<<grid, 256, FA_SMEM>>>(q, kh, vt, ah);
    }
    // 4) out = attn @ Wproj
    gemm_fp16<<<dim3(C_/128, M_ROWS/128), 128, GEMM_SMEM>>>(
        ah, wp, out, M_ROWS, C_, C_);
}

// round 8
// speedup vs baseline: 6.2212x; 1.1598x over previous
#include <cuda_runtime.h>
#include <cuda_fp16.h>
#include <math.h>
#include <stdint.h>

// Problem constants
#define B_   2
#define L_   2048
#define C_   1024
#define NH_  16
#define HD_  64
#define M_ROWS (B_*L_)          // 4096
#define QKV_N  (3*C_)           // 3072

// -------------------- scratch (static device globals) -----------------------
__device__ float  g_qkv [M_ROWS * QKV_N];     // fp32
__device__ float  g_q   [B_*NH_*L_*HD_];      // [b,h,l,d] fp32
__device__ __half g_kh  [B_*NH_*L_*HD_];      // [b,h,l,d] fp16
__device__ __half g_vh  [B_*NH_*L_*HD_];      // [b,h,l,d] fp16
__device__ __half g_vt  [B_*NH_*HD_*L_];      // [b,h,d,l] fp16 (transposed V)
__device__ __half g_xh  [M_ROWS * C_];        // x fp16 [M,K]
__device__ __half g_wq  [QKV_N * C_];         // Wqkv^T fp16 [N,K]
__device__ __half g_wp  [C_ * C_];            // Wproj^T fp16 [N,K]
__device__ __half g_ah  [M_ROWS * C_];        // attn fp16 [b,l,h,d] == [M,C]

// ======================= small helpers =====================================
__device__ __forceinline__ float ex2(float x) {
    float y; asm("ex2.approx.f32 %0, %1;" : "=f"(y) : "f"(x)); return y;
}
__device__ __forceinline__ uint32_t pack2(float a, float b) {
    __half2 h = __floats2half2_rn(a, b);
    return *(uint32_t*)&h;
}
__device__ __forceinline__ void mma16(float* c,
                                      uint32_t a0, uint32_t a1, uint32_t a2, uint32_t a3,
                                      uint32_t b0, uint32_t b1) {
    asm volatile(
        "mma.sync.aligned.m16n8k16.row.col.f32.f16.f16.f32 "
        "{%0,%1,%2,%3}, {%4,%5,%6,%7}, {%8,%9}, {%0,%1,%2,%3};"
        : "+f"(c[0]), "+f"(c[1]), "+f"(c[2]), "+f"(c[3])
        : "r"(a0), "r"(a1), "r"(a2), "r"(a3), "r"(b0), "r"(b1));
}
__device__ __forceinline__ void ldsm4(uint32_t& r0, uint32_t& r1,
                                      uint32_t& r2, uint32_t& r3, uint32_t addr) {
    asm volatile("ldmatrix.sync.aligned.m8n8.x4.shared.b16 {%0,%1,%2,%3}, [%4];"
        : "=r"(r0), "=r"(r1), "=r"(r2), "=r"(r3) : "r"(addr));
}
__device__ __forceinline__ void cpa16(void* smem, const void* gmem) {
    uint32_t s = (uint32_t)__cvta_generic_to_shared(smem);
    asm volatile("cp.async.cg.shared.global [%0], [%1], 16;" :: "r"(s), "l"(gmem));
}
#define CP_COMMIT() asm volatile("cp.async.commit_group;")
#define CP_WAIT0()  asm volatile("cp.async.wait_group 0;")
#define CP_WAIT1()  asm volatile("cp.async.wait_group 1;")

// ======================= prepass kernels ===================================
__global__ __launch_bounds__(256)
void cvt_half_kernel(const float4* __restrict__ in, uint2* __restrict__ out, int n4)
{
    int i = blockIdx.x * blockDim.x + threadIdx.x;
    if (i >= n4) return;
    float4 v = in[i];
    out[i] = make_uint2(pack2(v.x, v.y), pack2(v.z, v.w));
}

__global__ __launch_bounds__(256)
void transpose_half_kernel(const float* __restrict__ in, __half* __restrict__ out,
                           int R, int Ccols)
{
    __shared__ float tile[32][33];
    int tx = threadIdx.x & 31, ty = threadIdx.x >> 5;
    int c0 = blockIdx.x * 32, r0 = blockIdx.y * 32;
    #pragma unroll
    for (int j = ty; j < 32; j += 8)
        tile[j][tx] = in[(size_t)(r0 + j) * Ccols + c0 + tx];
    __syncthreads();
    #pragma unroll
    for (int j = ty; j < 32; j += 8)
        out[(size_t)(c0 + j) * R + r0 + tx] = __float2half(tile[tx][j]);
}

__global__ __launch_bounds__(256)
void vtrans_kernel(const __half* __restrict__ V, __half* __restrict__ VT)
{
    __shared__ __half tl[64][65];
    int bh = blockIdx.y;
    int l0 = blockIdx.x * 64;
    int tx = threadIdx.x & 63, ty = threadIdx.x >> 6;
    const __half* Vp = V + (size_t)bh * L_ * HD_;
    __half* Tp = VT + (size_t)bh * HD_ * L_;
    #pragma unroll
    for (int j = ty; j < 64; j += 4)
        tl[j][tx] = Vp[(size_t)(l0 + j) * HD_ + tx];
    __syncthreads();
    #pragma unroll
    for (int j = ty; j < 64; j += 4)
        Tp[(size_t)j * L_ + l0 + tx] = tl[tx][j];
}

// ======================= FP16 GEMM 128x128x32, 4 warps (64x64) =============
#define GBK 32
#define RSTR 20                         // words per smem row (40 halves, 80 B)
#define TSTW (128 * RSTR)               // words per operand tile: 2560
#define STW  (2 * TSTW)                 // words per stage: 5120 (20 KB)
#define GEMM_SMEM (3 * STW * 4)         // 61,440 B

__device__ __forceinline__ void gemm_load_tile(
    const __half* __restrict__ A, const __half* __restrict__ B,
    uint32_t* stage, int rowBase, int colBase, int k0, int K, int t)
{
    #pragma unroll
    for (int i = 0; i < 4; i++) {
        int idx = t + i * 128;
        int r = idx >> 2, c = idx & 3;
        cpa16(stage + r * RSTR + c * 4, A + (size_t)(rowBase + r) * K + k0 + c * 8);
    }
    #pragma unroll
    for (int i = 0; i < 4; i++) {
        int idx = t + i * 128;
        int r = idx >> 2, c = idx & 3;
        cpa16(stage + TSTW + r * RSTR + c * 4,
              B + (size_t)(colBase + r) * K + k0 + c * 8);
    }
}

__global__ __launch_bounds__(128)
void gemm_fp16(const __half* __restrict__ A, const __half* __restrict__ B,
               float* __restrict__ C, int M, int N, int K)
{
    extern __shared__ uint32_t smw[];

    const int t    = threadIdx.x;
    const int lane = t & 31;
    const int warp = t >> 5;
    const int grp  = lane >> 2;
    const int tig  = lane & 3;
    const int wm   = warp >> 1;
    const int wn   = warp & 1;
    const int rowBase = blockIdx.y * 128;
    const int colBase = blockIdx.x * 128;

    // ldmatrix lane offsets (bytes). Row stride 80 B.
    // A x4: mats = (r0-7,k0-7)(r8-15,k0-7)(r0-7,k8-15)(r8-15,k8-15)
    const int rowA = (lane & 7) + ((lane >> 3) & 1) * 8;
    const int kA   = ((lane >> 4) & 1) * 8;              // halves
    // B x4: mats = (n0-7,k0-7)(n0-7,k8-15)(n8-15,k0-7)(n8-15,k8-15)
    const int rowB = (lane & 7) + ((lane >> 4) & 1) * 8;
    const int kB   = ((lane >> 3) & 1) * 8;

    const uint32_t sbase = (uint32_t)__cvta_generic_to_shared(smw);
    const uint32_t aoff = (uint32_t)((wm * 64 + rowA) * 80 + kA * 2);
    const uint32_t boff = (uint32_t)(TSTW * 4 + (wn * 64 + rowB) * 80 + kB * 2);

    float acc[4][8][4];
    #pragma unroll
    for (int mi = 0; mi < 4; mi++)
        #pragma unroll
        for (int ni = 0; ni < 8; ni++)
            #pragma unroll
            for (int e = 0; e < 4; e++) acc[mi][ni][e] = 0.f;

    const int NIT = K / GBK;
    gemm_load_tile(A, B, smw,       rowBase, colBase, 0,   K, t); CP_COMMIT();
    gemm_load_tile(A, B, smw + STW, rowBase, colBase, GBK, K, t); CP_COMMIT();

    int scur = 0;
    for (int it = 0; it < NIT; ++it) {
        if (it < NIT - 1) { CP_WAIT1(); } else { CP_WAIT0(); }
        __syncthreads();

        if (it + 2 < NIT) {
            int snext = scur + 2; if (snext >= 3) snext -= 3;
            gemm_load_tile(A, B, smw + snext * STW, rowBase, colBase,
                           (it + 2) * GBK, K, t);
            CP_COMMIT();
        }

        const uint32_t Abase = sbase + scur * (STW * 4) + aoff;
        const uint32_t Bbase = sbase + scur * (STW * 4) + boff;

        #pragma unroll
        for (int ks = 0; ks < 2; ks++) {        // k-steps of 16 (32 B)
            uint32_t af[4][4];
            #pragma unroll
            for (int mi = 0; mi < 4; mi++)
                ldsm4(af[mi][0], af[mi][1], af[mi][2], af[mi][3],
                      Abase + mi * (16 * 80) + ks * 32);
            uint32_t bf[8][2];
            #pragma unroll
            for (int nip = 0; nip < 4; nip++)
                ldsm4(bf[2*nip][0], bf[2*nip][1], bf[2*nip+1][0], bf[2*nip+1][1],
                      Bbase + nip * (16 * 80) + ks * 32);
            #pragma unroll
            for (int mi = 0; mi < 4; mi++)
                #pragma unroll
                for (int ni = 0; ni < 8; ni++)
                    mma16(acc[mi][ni], af[mi][0], af[mi][1], af[mi][2], af[mi][3],
                          bf[ni][0], bf[ni][1]);
        }
        scur++; if (scur >= 3) scur -= 3;
    }

    #pragma unroll
    for (int mi = 0; mi < 4; mi++) {
        #pragma unroll
        for (int ni = 0; ni < 8; ni++) {
            int row = rowBase + wm * 64 + mi * 16 + grp;
            int col = colBase + wn * 64 + ni * 8 + 2 * tig;
            *(float2*)&C[(size_t)row       * N + col] = make_float2(acc[mi][ni][0], acc[mi][ni][1]);
            *(float2*)&C[(size_t)(row + 8) * N + col] = make_float2(acc[mi][ni][2], acc[mi][ni][3]);
        }
    }
}

// ======================= RoPE + head split =================================
__global__ __launch_bounds__(256)
void rope_split_kernel(const float* __restrict__ qkv,
                       float* __restrict__ Q, __half* __restrict__ Kh,
                       __half* __restrict__ Vh)
{
    int idx = blockIdx.x * blockDim.x + threadIdx.x;
    const int total = M_ROWS * NH_ * (HD_/2);
    if (idx >= total) return;

    int i  = idx & 31;
    int h  = (idx >> 5) & 15;
    int bl = idx >> 9;
    int b  = bl >> 11;
    int l  = bl & 2047;

    const float* row = qkv + (size_t)bl * QKV_N;
    int d0 = 2*i;

    float qe = row[h*HD_ + d0],          qo = row[h*HD_ + d0 + 1];
    float ke = row[C_   + h*HD_ + d0],   ko = row[C_   + h*HD_ + d0 + 1];
    float ve = row[2*C_ + h*HD_ + d0],   vo = row[2*C_ + h*HD_ + d0 + 1];

    double inv_freq = exp(-((double)d0 / 64.0) * log(10000.0));
    float theta = (float)((double)l * inv_freq);
    float s, c;
    sincosf(theta, &s, &c);

    // reference convention (sin/cos swapped):
    float qe2 = qe*s - qo*c,  qo2 = qe*c + qo*s;
    float ke2 = ke*s - ko*c,  ko2 = ke*c + ko*s;

    size_t o = (((size_t)(b*NH_ + h) * L_) + l) * HD_ + d0;
    Q[o] = qe2;  Q[o+1] = qo2;
    *(__half2*)&Kh[o] = __floats2half2_rn(ke2, ko2);
    *(__half2*)&Vh[o] = __floats2half2_rn(ve, vo);
}

// ======================= Flash attention (fp16 mma, causal) ================
// Q tile 128 rows, 8 warps x 16 rows; K/VT double-buffered; P register-resident.
#define FSTR 36                         // words per smem row (72 halves, 144 B)
#define KT_W (64 * FSTR)                // words per K or VT stage: 2304
#define OFF_VT (2 * KT_W)
#define FA_SMEM (4 * KT_W * 4)          // 36,864 B

__global__ __launch_bounds__(256)
void flash_fp16(const float* __restrict__ Q, const __half* __restrict__ K,
                const __half* __restrict__ VT, __half* __restrict__ O)
{
    extern __shared__ uint32_t smw[];
    uint32_t* Ksm = smw;                 // [2][64][FSTR]
    uint32_t* Vsm = smw + OFF_VT;        // [2][64][FSTR]

    const int t    = threadIdx.x;
    const int lane = t & 31;
    const int warp = t >> 5;
    const int grp  = lane >> 2;
    const int tig  = lane & 3;
    const int qt   = (gridDim.x - 1) - blockIdx.x;
    const int bh   = blockIdx.y;
    const size_t base = (size_t)bh * L_ * HD_;
    const int R0 = qt * 128 + warp * 16;

    // ldmatrix B-operand lane offsets (row stride 144 B)
    const int rowB = (lane & 7) + ((lane >> 4) & 1) * 8;
    const int kB   = ((lane >> 3) & 1) * 8;
    const uint32_t sbase = (uint32_t)__cvta_generic_to_shared(smw);
    const uint32_t lboff = (uint32_t)(rowB * 144 + kB * 2);

    // Q fragments (scale*log2e folded), packed fp16
    const float qsc = 0.125f * 1.4426950408889634f;
    uint32_t aq[4][4];
    {
        const float* Qp = Q + base + (size_t)R0 * HD_;
        #pragma unroll
        for (int ks = 0; ks < 4; ks++) {
            int c = 16 * ks + 2 * tig;
            aq[ks][0] = pack2(Qp[(grp    ) * HD_ + c    ] * qsc, Qp[(grp    ) * HD_ + c + 1] * qsc);
            aq[ks][1] = pack2(Qp[(grp + 8) * HD_ + c    ] * qsc, Qp[(grp + 8) * HD_ + c + 1] * qsc);
            aq[ks][2] = pack2(Qp[(grp    ) * HD_ + c + 8] * qsc, Qp[(grp    ) * HD_ + c + 9] * qsc);
            aq[ks][3] = pack2(Qp[(grp + 8) * HD_ + c + 8] * qsc, Qp[(grp + 8) * HD_ + c + 9] * qsc);
        }
    }

    float o[8][4];
    #pragma unroll
    for (int ni = 0; ni < 8; ni++)
        #pragma unroll
        for (int e = 0; e < 4; e++) o[ni][e] = 0.f;
    float mA = -1e30f, mB = -1e30f, lA = 0.f, lB = 0.f;

    const int nkt = 2 * qt + 2;

    {
        const __half* Kg = K + base;
        const __half* Vg = VT + (size_t)bh * HD_ * L_;
        #pragma unroll
        for (int i = 0; i < 2; i++) {
            int idx = t + i * 256;
            int r = idx >> 3, c = idx & 7;
            cpa16(Ksm + r * FSTR + c * 4, Kg + (size_t)r * HD_ + c * 8);
            cpa16(Vsm + r * FSTR + c * 4, Vg + (size_t)r * L_ + c * 8);
        }
        CP_COMMIT();
    }

    for (int kt = 0; kt < nkt; kt++) {
        const int p = kt & 1;
        CP_WAIT0();
        __syncthreads();

        if (kt + 1 < nkt) {
            const __half* Kg = K + base + (size_t)(kt + 1) * 64 * HD_;
            const __half* Vg = VT + (size_t)bh * HD_ * L_ + (size_t)(kt + 1) * 64;
            uint32_t* Kn = Ksm + (p ^ 1) * KT_W;
            uint32_t* Vn = Vsm + (p ^ 1) * KT_W;
            #pragma unroll
            for (int i = 0; i < 2; i++) {
                int idx = t + i * 256;
                int r = idx >> 3, c = idx & 7;
                cpa16(Kn + r * FSTR + c * 4, Kg + (size_t)r * HD_ + c * 8);
                cpa16(Vn + r * FSTR + c * 4, Vg + (size_t)r * L_ + c * 8);
            }
            CP_COMMIT();
        }

        const uint32_t Kbase = sbase + p * (KT_W * 4) + lboff;
        const uint32_t Vbase = sbase + (OFF_VT + p * KT_W) * 4 + lboff;

        const bool active = (kt * 64 <= R0 + 15);
        if (active) {
            // ---- S = Q K^T (16 x 64 per warp) ----
            float s[8][4];
            #pragma unroll
            for (int ni = 0; ni < 8; ni++)
                #pragma unroll
                for (int e = 0; e < 4; e++) s[ni][e] = 0.f;

            #pragma unroll
            for (int ks = 0; ks < 4; ks++) {
                uint32_t bf[8][2];
                #pragma unroll
                for (int nip = 0; nip < 4; nip++)
                    ldsm4(bf[2*nip][0], bf[2*nip][1], bf[2*nip+1][0], bf[2*nip+1][1],
                          Kbase + nip * (16 * 144) + ks * 32);
                #pragma unroll
                for (int ni = 0; ni < 8; ni++)
                    mma16(s[ni], aq[ks][0], aq[ks][1], aq[ks][2], aq[ks][3],
                          bf[ni][0], bf[ni][1]);
            }

            // causal mask near the diagonal
            if (kt * 64 + 63 > R0) {
                #pragma unroll
                for (int ni = 0; ni < 8; ni++)
                    #pragma unroll
                    for (int e = 0; e < 4; e++) {
                        int col = kt*64 + ni*8 + 2*tig + (e & 1);
                        int row = R0 + grp + ((e & 2) ? 8 : 0);
                        if (col > row) s[ni][e] = -1e30f;
                    }
            }

            // ---- online softmax (exp2 domain) ----
            float mxA = -1e30f, mxB = -1e30f;
            #pragma unroll
            for (int ni = 0; ni < 8; ni++) {
                mxA = fmaxf(mxA, fmaxf(s[ni][0], s[ni][1]));
                mxB = fmaxf(mxB, fmaxf(s[ni][2], s[ni][3]));
            }
            mxA = fmaxf(mxA, __shfl_xor_sync(0xffffffffu, mxA, 1));
            mxA = fmaxf(mxA, __shfl_xor_sync(0xffffffffu, mxA, 2));
            mxB = fmaxf(mxB, __shfl_xor_sync(0xffffffffu, mxB, 1));
            mxB = fmaxf(mxB, __shfl_xor_sync(0xffffffffu, mxB, 2));

            float mnA = fmaxf(mA, mxA), mnB = fmaxf(mB, mxB);
            float aA = ex2(mA - mnA), aB = ex2(mB - mnB);
            float sA = 0.f, sB = 0.f;
            #pragma unroll
            for (int ni = 0; ni < 8; ni++) {
                s[ni][0] = ex2(s[ni][0] - mnA);
                s[ni][1] = ex2(s[ni][1] - mnA);
                s[ni][2] = ex2(s[ni][2] - mnB);
                s[ni][3] = ex2(s[ni][3] - mnB);
                sA += s[ni][0] + s[ni][1];
                sB += s[ni][2] + s[ni][3];
            }
            sA += __shfl_xor_sync(0xffffffffu, sA, 1);
            sA += __shfl_xor_sync(0xffffffffu, sA, 2);
            sB += __shfl_xor_sync(0xffffffffu, sB, 1);
            sB += __shfl_xor_sync(0xffffffffu, sB, 2);
            lA = lA * aA + sA;  lB = lB * aB + sB;
            mA = mnA;           mB = mnB;
            #pragma unroll
            for (int ni = 0; ni < 8; ni++) {
                o[ni][0] *= aA; o[ni][1] *= aA;
                o[ni][2] *= aB; o[ni][3] *= aB;
            }

            // ---- O += P V : P fragments straight from registers ----
            #pragma unroll
            for (int ks = 0; ks < 4; ks++) {
                uint32_t a0 = pack2(s[2*ks  ][0], s[2*ks  ][1]);
                uint32_t a1 = pack2(s[2*ks  ][2], s[2*ks  ][3]);
                uint32_t a2 = pack2(s[2*ks+1][0], s[2*ks+1][1]);
                uint32_t a3 = pack2(s[2*ks+1][2], s[2*ks+1][3]);
                uint32_t bf[8][2];
                #pragma unroll
                for (int nip = 0; nip < 4; nip++)
                    ldsm4(bf[2*nip][0], bf[2*nip][1], bf[2*nip+1][0], bf[2*nip+1][1],
                          Vbase + nip * (16 * 144) + ks * 32);
                #pragma unroll
                for (int ni = 0; ni < 8; ni++)
                    mma16(o[ni], a0, a1, a2, a3, bf[ni][0], bf[ni][1]);
            }
        }
    }

    // epilogue: normalize, write attn fp16 [b, l, h, d]
    int b = bh >> 4, h = bh & 15;
    float iA = 1.f / lA, iB = 1.f / lB;
    #pragma unroll
    for (int ni = 0; ni < 8; ni++) {
        int c = ni*8 + 2*tig;
        size_t offA = ((size_t)(b*L_ + R0 + grp    )) * C_ + h*HD_ + c;
        size_t offB = ((size_t)(b*L_ + R0 + grp + 8)) * C_ + h*HD_ + c;
        *(uint32_t*)&O[offA] = pack2(o[ni][0]*iA, o[ni][1]*iA);
        *(uint32_t*)&O[offB] = pack2(o[ni][2]*iB, o[ni][3]*iB);
    }
}

// ======================= launcher ==========================================
extern "C" void kernel_launch(void* const* d_in, const int* in_sizes, int n_in,
                              void* d_out, int out_size)
{
    const float* x     = (const float*)d_in[0];
    const float* Wqkv  = (const float*)d_in[1];
    const float* Wproj = (const float*)d_in[2];
    float* out = (float*)d_out;

    float *qkv, *q;
    __half *kh, *vh, *vt, *xh, *wq, *wp, *ah;
    cudaGetSymbolAddress((void**)&qkv, g_qkv);
    cudaGetSymbolAddress((void**)&q,   g_q);
    cudaGetSymbolAddress((void**)&kh,  g_kh);
    cudaGetSymbolAddress((void**)&vh,  g_vh);
    cudaGetSymbolAddress((void**)&vt,  g_vt);
    cudaGetSymbolAddress((void**)&xh,  g_xh);
    cudaGetSymbolAddress((void**)&wq,  g_wq);
    cudaGetSymbolAddress((void**)&wp,  g_wp);
    cudaGetSymbolAddress((void**)&ah,  g_ah);

    cudaFuncSetAttribute(gemm_fp16,
                         cudaFuncAttributeMaxDynamicSharedMemorySize, GEMM_SMEM);
    cudaFuncSetAttribute(flash_fp16,
                         cudaFuncAttributeMaxDynamicSharedMemorySize, FA_SMEM);

    // 0) convert x to fp16; transpose weights to [N,K] fp16
    {
        int n4 = (M_ROWS * C_) / 4;
        cvt_half_kernel<<<(n4 + 255)/256, 256>>>((const float4*)x, (uint2*)xh, n4);
        transpose_half_kernel<<<dim3(QKV_N/32, C_/32), 256>>>(Wqkv, wq, C_, QKV_N);
        transpose_half_kernel<<<dim3(C_/32,   C_/32), 256>>>(Wproj, wp, C_, C_);
    }
    // 1) qkv = x @ Wqkv
    gemm_fp16<<<dim3(QKV_N/128, M_ROWS/128), 128, GEMM_SMEM>>>(
        xh, wq, qkv, M_ROWS, QKV_N, C_);
    // 2) RoPE + head split
    {
        int total = M_ROWS * NH_ * (HD_/2);
        rope_split_kernel<<<(total + 255) / 256, 256>>>(qkv, q, kh, vh);
    }
    // 2b) V transpose -> [b,h,d,l]
    vtrans_kernel<<<dim3(L_/64, B_*NH_), 256>>>(vh, vt);
    // 3) causal flash attention -> attn fp16
    {
        dim3 grid(L_ / 128, B_ * NH_);
        flash_fp16<<<grid, 256, FA_SMEM>>>(q, kh, vt, ah);
    }
    // 4) out = attn @ Wproj
    gemm_fp16<<<dim3(C_/128, M_ROWS/128), 128, GEMM_SMEM>>>(
        ah, wp, out, M_ROWS, C_, C_);
}